// round 1
// baseline (speedup 1.0000x reference)
#include <cuda_runtime.h>
#include <math.h>

#define LSEQ 1024
#define DMODEL 768
#define NHEAD 12
#define HDIM 64
#define NLAYER 12

// ---------------- scratch (device globals; no allocation) ----------------
__device__ float g_x[LSEQ * DMODEL];        // residual stream
__device__ float g_h[LSEQ * DMODEL];        // layernorm output
__device__ float g_qkv[LSEQ * 3 * DMODEL];  // qkv projection
__device__ float g_attn[LSEQ * DMODEL];     // attention output (pre-proj)
__device__ float g_fc[LSEQ * 4 * DMODEL];   // MLP hidden
__device__ float g_sc[NHEAD * LSEQ * LSEQ]; // attention scores / probs

// ---------------- embedding ----------------
__global__ void embed_kernel(const int* __restrict__ ids,
                             const int* __restrict__ start_pos,
                             const float* __restrict__ wte,
                             const float* __restrict__ wpe) {
    int l = blockIdx.x;
    const float* we = wte + (long)ids[l] * DMODEL;
    const float* pe = wpe + (long)(start_pos[0] + l) * DMODEL;
    float* xr = g_x + (long)l * DMODEL;
    for (int d = threadIdx.x; d < DMODEL; d += blockDim.x)
        xr[d] = we[d] + pe[d];
}

// ---------------- layernorm (one block per row) ----------------
__global__ void ln_kernel(const float* __restrict__ in, float* __restrict__ out,
                          const float* __restrict__ g, const float* __restrict__ b) {
    int l = blockIdx.x;
    int t = threadIdx.x;
    const float* row = in + (long)l * DMODEL;
    __shared__ float r1[256], r2[256];
    float s = 0.f, s2 = 0.f;
    for (int d = t; d < DMODEL; d += 256) {
        float v = row[d];
        s += v; s2 += v * v;
    }
    r1[t] = s; r2[t] = s2;
    __syncthreads();
    for (int o = 128; o > 0; o >>= 1) {
        if (t < o) { r1[t] += r1[t + o]; r2[t] += r2[t + o]; }
        __syncthreads();
    }
    float mean = r1[0] * (1.f / DMODEL);
    float var  = r2[0] * (1.f / DMODEL) - mean * mean;
    float inv = rsqrtf(var + 1e-5f);
    float* orow = out + (long)l * DMODEL;
    for (int d = t; d < DMODEL; d += 256)
        orow[d] = (row[d] - mean) * inv * g[d] + b[d];
}

// ---------------- row softmax over g_sc (1024-wide rows) ----------------
__global__ void softmax_kernel() {
    long row = blockIdx.x;                 // 0 .. NHEAD*LSEQ-1
    float* s = g_sc + row * (long)LSEQ;
    int t = threadIdx.x;
    float4 v = *(const float4*)(s + t * 4);
    __shared__ float red[256];
    float m = fmaxf(fmaxf(v.x, v.y), fmaxf(v.z, v.w));
    red[t] = m;
    __syncthreads();
    for (int o = 128; o > 0; o >>= 1) {
        if (t < o) red[t] = fmaxf(red[t], red[t + o]);
        __syncthreads();
    }
    m = red[0];
    __syncthreads();
    float4 e;
    e.x = expf(v.x - m); e.y = expf(v.y - m);
    e.z = expf(v.z - m); e.w = expf(v.w - m);
    red[t] = e.x + e.y + e.z + e.w;
    __syncthreads();
    for (int o = 128; o > 0; o >>= 1) {
        if (t < o) red[t] += red[t + o];
        __syncthreads();
    }
    float inv = 1.f / red[0];
    e.x *= inv; e.y *= inv; e.z *= inv; e.w *= inv;
    *(float4*)(s + t * 4) = e;
}

// ---------------- generic tiled GEMM ----------------
// C[z] = A[z] @ B[z] (+bias)(+res)(gelu / causal-scale)  — 64x64x16 tiles
// EPI: 0=bias, 1=bias+residual add, 2=bias+gelu(tanh), 3=scale+causal mask
// TB : B stored [N,K] row-major (dot-product form) instead of [K,N]
__device__ __forceinline__ float gelu_f(float v) {
    float c = 0.7978845608028654f * (v + 0.044715f * v * v * v);
    return 0.5f * v * (1.f + tanhf(c));
}

template <int EPI, bool TB>
__global__ void gemm_kernel(const float* __restrict__ A, const float* __restrict__ B,
                            const float* __restrict__ bias, const float* __restrict__ res,
                            float* __restrict__ C,
                            int M, int N, int K, int lda, int ldb, int ldc,
                            long az, long bz, long cz) {
    int z = blockIdx.z;
    A += (long)z * az;
    B += (long)z * bz;
    C += (long)z * cz;

    int m0 = blockIdx.y * 64;
    int n0 = blockIdx.x * 64;
    int tid = threadIdx.x;
    int tx = tid & 15;       // 0..15
    int ty = tid >> 4;       // 0..15

    __shared__ float As[16][64];
    __shared__ float Bs[16][68];   // padded

    float acc[4][4] = {};
    int ar = tid >> 2;       // 0..63
    int ac = tid & 3;        // 0..3

    for (int k0 = 0; k0 < K; k0 += 16) {
        // A tile: 64 rows x 16 k (float4 per thread), stored k-major
        float4 a4 = *(const float4*)(A + (long)(m0 + ar) * lda + k0 + ac * 4);
        As[ac * 4 + 0][ar] = a4.x;
        As[ac * 4 + 1][ar] = a4.y;
        As[ac * 4 + 2][ar] = a4.z;
        As[ac * 4 + 3][ar] = a4.w;

        if (TB) {
            // B[N,K]: 64 n-rows x 16 k, transpose into k-major
            float4 b4 = make_float4(0.f, 0.f, 0.f, 0.f);
            if (n0 + ar < N)
                b4 = *(const float4*)(B + (long)(n0 + ar) * ldb + k0 + ac * 4);
            Bs[ac * 4 + 0][ar] = b4.x;
            Bs[ac * 4 + 1][ar] = b4.y;
            Bs[ac * 4 + 2][ar] = b4.z;
            Bs[ac * 4 + 3][ar] = b4.w;
        } else {
            // B[K,N]: 16 k-rows x 64 n (float4 per thread)
            int kr = tid >> 4;   // 0..15
            int nc = tid & 15;   // 0..15
            float4 b4 = make_float4(0.f, 0.f, 0.f, 0.f);
            if (n0 + nc * 4 < N)
                b4 = *(const float4*)(B + (long)(k0 + kr) * ldb + n0 + nc * 4);
            *(float4*)&Bs[kr][nc * 4] = b4;
        }
        __syncthreads();

#pragma unroll
        for (int kk = 0; kk < 16; kk++) {
            float av[4], bv[4];
            *(float4*)av = *(const float4*)&As[kk][ty * 4];
            *(float4*)bv = *(const float4*)&Bs[kk][tx * 4];
#pragma unroll
            for (int i = 0; i < 4; i++)
#pragma unroll
                for (int j = 0; j < 4; j++)
                    acc[i][j] = fmaf(av[i], bv[j], acc[i][j]);
        }
        __syncthreads();
    }

#pragma unroll
    for (int i = 0; i < 4; i++) {
        int r = m0 + ty * 4 + i;
#pragma unroll
        for (int j = 0; j < 4; j++) {
            int c = n0 + tx * 4 + j;
            if (c >= N) continue;
            float v = acc[i][j];
            if (EPI == 3) {
                v *= 0.125f;                       // 1/sqrt(64)
                if (c > r) v = -INFINITY;          // causal mask
            } else {
                if (bias) v += bias[c];
                if (EPI == 1) v += res[(long)r * ldc + c];
                if (EPI == 2) v = gelu_f(v);
            }
            C[(long)r * ldc + c] = v;
        }
    }
}

// ---------------- host launcher ----------------
extern "C" void kernel_launch(void* const* d_in, const int* in_sizes, int n_in,
                              void* d_out, int out_size) {
    const int*   ids    = (const int*)d_in[0];
    const int*   sp     = (const int*)d_in[1];
    // d_in[2] block_ids, d_in[3] kv_k_pool, d_in[4] kv_v_pool: identity map at
    // start_pos=0 and pools are input-only -> attention uses fresh K/V directly.
    const float* wte    = (const float*)d_in[5];
    const float* wpe    = (const float*)d_in[6];
    const float* ln1_g  = (const float*)d_in[7];
    const float* ln1_b  = (const float*)d_in[8];
    const float* attn_w = (const float*)d_in[9];
    const float* attn_b = (const float*)d_in[10];
    const float* attn_pw= (const float*)d_in[11];
    const float* attn_pb= (const float*)d_in[12];
    const float* ln2_g  = (const float*)d_in[13];
    const float* ln2_b  = (const float*)d_in[14];
    const float* fc_w   = (const float*)d_in[15];
    const float* fc_b   = (const float*)d_in[16];
    const float* proj_w = (const float*)d_in[17];
    const float* proj_b = (const float*)d_in[18];
    const float* lnf_g  = (const float*)d_in[19];
    const float* lnf_b  = (const float*)d_in[20];
    float* out = (float*)d_out;

    float *x, *h, *qkv, *attn, *fc, *sc;
    cudaGetSymbolAddress((void**)&x,    g_x);
    cudaGetSymbolAddress((void**)&h,    g_h);
    cudaGetSymbolAddress((void**)&qkv,  g_qkv);
    cudaGetSymbolAddress((void**)&attn, g_attn);
    cudaGetSymbolAddress((void**)&fc,   g_fc);
    cudaGetSymbolAddress((void**)&sc,   g_sc);

    const int D = DMODEL;

    embed_kernel<<<LSEQ, 256>>>(ids, sp, wte, wpe);

    for (int i = 0; i < NLAYER; i++) {
        // h = ln1(x)
        ln_kernel<<<LSEQ, 256>>>(x, h, ln1_g + i * D, ln1_b + i * D);

        // qkv = h @ attn_w[i] + attn_b[i]      [1024, 2304]
        gemm_kernel<0, false><<<dim3(36, 16, 1), 256>>>(
            h, attn_w + (long)i * D * 3 * D, attn_b + (long)i * 3 * D, nullptr, qkv,
            LSEQ, 3 * D, D, D, 3 * D, 3 * D, 0, 0, 0);

        // scores[h] = scale * Q Kᵀ with causal mask   (batched over 12 heads)
        gemm_kernel<3, true><<<dim3(16, 16, NHEAD), 256>>>(
            qkv, qkv + D, nullptr, nullptr, sc,
            LSEQ, LSEQ, HDIM, 3 * D, 3 * D, LSEQ,
            HDIM, HDIM, (long)LSEQ * LSEQ);

        // softmax over each of 12*1024 rows
        softmax_kernel<<<NHEAD * LSEQ, 256>>>();

        // attn[l, h*64+d] = P @ V                    (batched over heads)
        gemm_kernel<0, false><<<dim3(1, 16, NHEAD), 256>>>(
            sc, qkv + 2 * D, nullptr, nullptr, attn,
            LSEQ, HDIM, LSEQ, LSEQ, 3 * D, D,
            (long)LSEQ * LSEQ, HDIM, HDIM);

        // x = x + attn @ attn_pw[i] + attn_pb[i]
        gemm_kernel<1, false><<<dim3(12, 16, 1), 256>>>(
            attn, attn_pw + (long)i * D * D, attn_pb + (long)i * D, x, x,
            LSEQ, D, D, D, D, D, 0, 0, 0);

        // h = ln2(x)
        ln_kernel<<<LSEQ, 256>>>(x, h, ln2_g + i * D, ln2_b + i * D);

        // fc = gelu(h @ fc_w[i] + fc_b[i])           [1024, 3072]
        gemm_kernel<2, false><<<dim3(48, 16, 1), 256>>>(
            h, fc_w + (long)i * D * 4 * D, fc_b + (long)i * 4 * D, nullptr, fc,
            LSEQ, 4 * D, D, D, 4 * D, 4 * D, 0, 0, 0);

        // x = x + fc @ proj_w[i] + proj_b[i]
        gemm_kernel<1, false><<<dim3(12, 16, 1), 256>>>(
            fc, proj_w + (long)i * 4 * D * D, proj_b + (long)i * D, x, x,
            LSEQ, D, 4 * D, 4 * D, D, D, 0, 0, 0);
    }

    // h = lnf(x);  logits = h @ wteᵀ   [1024, 50257]
    ln_kernel<<<LSEQ, 256>>>(x, h, lnf_g, lnf_b);
    gemm_kernel<0, true><<<dim3((50257 + 63) / 64, 16, 1), 256>>>(
        h, wte, nullptr, nullptr, out,
        LSEQ, 50257, D, D, D, 50257, 0, 0, 0);
}

// round 3
// speedup vs baseline: 2.3391x; 2.3391x over previous
#include <cuda_runtime.h>
#include <cuda_bf16.h>
#include <math.h>
#include <stdint.h>

#define LSEQ 1024
#define DMODEL 768
#define NHEAD 12
#define HDIM 64
#define NLAYER 12
#define VOCAB 50257

typedef __nv_bfloat16 bf16;
typedef __nv_bfloat162 bf162;

// ---------------- scratch (device globals; no allocation) ----------------
__device__ float g_x[LSEQ * DMODEL];                 // residual stream (fp32)
__device__ bf16  g_h_hi[LSEQ * DMODEL],  g_h_lo[LSEQ * DMODEL];
__device__ bf16  g_qkv_hi[LSEQ * 3 * DMODEL], g_qkv_lo[LSEQ * 3 * DMODEL];
__device__ bf16  g_attn_hi[LSEQ * DMODEL], g_attn_lo[LSEQ * DMODEL];
__device__ bf16  g_fc_hi[LSEQ * 4 * DMODEL], g_fc_lo[LSEQ * 4 * DMODEL];
__device__ float g_sc[NHEAD * LSEQ * LSEQ];          // attention scores (fp32)
__device__ bf16  g_sp_hi[NHEAD * LSEQ * LSEQ], g_sp_lo[NHEAD * LSEQ * LSEQ];

// pre-converted weights (hi/lo bf16)
__device__ bf16 w_qkv_hi[NLAYER * DMODEL * 3 * DMODEL], w_qkv_lo[NLAYER * DMODEL * 3 * DMODEL];
__device__ bf16 w_pw_hi [NLAYER * DMODEL * DMODEL],     w_pw_lo [NLAYER * DMODEL * DMODEL];
__device__ bf16 w_fc_hi [NLAYER * DMODEL * 4 * DMODEL], w_fc_lo [NLAYER * DMODEL * 4 * DMODEL];
__device__ bf16 w_pj_hi [NLAYER * 4 * DMODEL * DMODEL], w_pj_lo [NLAYER * 4 * DMODEL * DMODEL];
__device__ bf16 w_te_hi [(long)VOCAB * DMODEL],         w_te_lo [(long)VOCAB * DMODEL];

// ---------------- helpers ----------------
__device__ __forceinline__ void split_bf(float v, bf16& h, bf16& l) {
    h = __float2bfloat16(v);
    l = __float2bfloat16(v - __bfloat162float(h));
}

// ---------------- weight conversion (fp32 -> hi/lo bf16) ----------------
__global__ void f2bf_kernel(const float4* __restrict__ src,
                            bf162* __restrict__ hi, bf162* __restrict__ lo, long n4) {
    long i = (long)blockIdx.x * blockDim.x + threadIdx.x;
    if (i >= n4) return;
    float4 v = src[i];
    bf16 hx, lx, hy, ly, hz, lz, hw, lw;
    split_bf(v.x, hx, lx); split_bf(v.y, hy, ly);
    split_bf(v.z, hz, lz); split_bf(v.w, hw, lw);
    bf162 a; a.x = hx; a.y = hy;
    bf162 b; b.x = hz; b.y = hw;
    hi[i * 2] = a; hi[i * 2 + 1] = b;
    a.x = lx; a.y = ly; b.x = lz; b.y = lw;
    lo[i * 2] = a; lo[i * 2 + 1] = b;
}

// ---------------- embedding ----------------
__global__ void embed_kernel(const int* __restrict__ ids,
                             const int* __restrict__ start_pos,
                             const float* __restrict__ wte,
                             const float* __restrict__ wpe) {
    int l = blockIdx.x;
    const float* we = wte + (long)ids[l] * DMODEL;
    const float* pe = wpe + (long)(start_pos[0] + l) * DMODEL;
    float* xr = g_x + (long)l * DMODEL;
    for (int d = threadIdx.x; d < DMODEL; d += blockDim.x)
        xr[d] = we[d] + pe[d];
}

// ---------------- layernorm: fp32 in -> hi/lo bf16 out ----------------
__global__ void ln_kernel(const float* __restrict__ in,
                          bf16* __restrict__ oh, bf16* __restrict__ ol,
                          const float* __restrict__ g, const float* __restrict__ b) {
    int l = blockIdx.x;
    int t = threadIdx.x;
    const float* row = in + (long)l * DMODEL;
    __shared__ float r1[256], r2[256];
    float s = 0.f, s2 = 0.f;
    for (int d = t; d < DMODEL; d += 256) {
        float v = row[d];
        s += v; s2 += v * v;
    }
    r1[t] = s; r2[t] = s2;
    __syncthreads();
    for (int o = 128; o > 0; o >>= 1) {
        if (t < o) { r1[t] += r1[t + o]; r2[t] += r2[t + o]; }
        __syncthreads();
    }
    float mean = r1[0] * (1.f / DMODEL);
    float var  = r2[0] * (1.f / DMODEL) - mean * mean;
    float inv = rsqrtf(var + 1e-5f);
    for (int d = t; d < DMODEL; d += 256) {
        float v = (row[d] - mean) * inv * g[d] + b[d];
        bf16 h, lo2; split_bf(v, h, lo2);
        oh[(long)l * DMODEL + d] = h;
        ol[(long)l * DMODEL + d] = lo2;
    }
}

// ---------------- row softmax: fp32 scores -> hi/lo bf16 probs ----------------
__global__ void softmax_kernel() {
    long row = blockIdx.x;
    const float* s = g_sc + row * (long)LSEQ;
    bf16* ph = g_sp_hi + row * (long)LSEQ;
    bf16* pl = g_sp_lo + row * (long)LSEQ;
    int t = threadIdx.x;
    float4 v = *(const float4*)(s + t * 4);
    __shared__ float red[256];
    float m = fmaxf(fmaxf(v.x, v.y), fmaxf(v.z, v.w));
    red[t] = m;
    __syncthreads();
    for (int o = 128; o > 0; o >>= 1) {
        if (t < o) red[t] = fmaxf(red[t], red[t + o]);
        __syncthreads();
    }
    m = red[0];
    __syncthreads();
    float4 e;
    e.x = expf(v.x - m); e.y = expf(v.y - m);
    e.z = expf(v.z - m); e.w = expf(v.w - m);
    red[t] = e.x + e.y + e.z + e.w;
    __syncthreads();
    for (int o = 128; o > 0; o >>= 1) {
        if (t < o) red[t] += red[t + o];
        __syncthreads();
    }
    float inv = 1.f / red[0];
    e.x *= inv; e.y *= inv; e.z *= inv; e.w *= inv;
    bf16 h0, l0, h1, l1, h2, l2, h3, l3;
    split_bf(e.x, h0, l0); split_bf(e.y, h1, l1);
    split_bf(e.z, h2, l2); split_bf(e.w, h3, l3);
    bf162 a; a.x = h0; a.y = h1; *(bf162*)(ph + t * 4) = a;
    a.x = h2; a.y = h3;          *(bf162*)(ph + t * 4 + 2) = a;
    a.x = l0; a.y = l1;          *(bf162*)(pl + t * 4) = a;
    a.x = l2; a.y = l3;          *(bf162*)(pl + t * 4 + 2) = a;
}

__device__ __forceinline__ float gelu_f(float v) {
    float c = 0.7978845608028654f * (v + 0.044715f * v * v * v);
    return 0.5f * v * (1.f + tanhf(c));
}

#define CPA16(dst, src, sz) \
    asm volatile("cp.async.cg.shared.global [%0], [%1], 16, %2;\n" \
                 :: "r"(dst), "l"(src), "r"(sz))

__device__ __forceinline__ void ldsm4(uint32_t& r0, uint32_t& r1, uint32_t& r2, uint32_t& r3,
                                      uint32_t addr) {
    asm volatile("ldmatrix.sync.aligned.m8n8.x4.shared.b16 {%0,%1,%2,%3}, [%4];"
                 : "=r"(r0), "=r"(r1), "=r"(r2), "=r"(r3) : "r"(addr));
}
__device__ __forceinline__ void ldsm4t(uint32_t& r0, uint32_t& r1, uint32_t& r2, uint32_t& r3,
                                       uint32_t addr) {
    asm volatile("ldmatrix.sync.aligned.m8n8.x4.trans.shared.b16 {%0,%1,%2,%3}, [%4];"
                 : "=r"(r0), "=r"(r1), "=r"(r2), "=r"(r3) : "r"(addr));
}
__device__ __forceinline__ void mma16816(float* c, const uint32_t* a, const uint32_t* b) {
    asm volatile(
        "mma.sync.aligned.m16n8k16.row.col.f32.bf16.bf16.f32 "
        "{%0,%1,%2,%3}, {%4,%5,%6,%7}, {%8,%9}, {%0,%1,%2,%3};\n"
        : "+f"(c[0]), "+f"(c[1]), "+f"(c[2]), "+f"(c[3])
        : "r"(a[0]), "r"(a[1]), "r"(a[2]), "r"(a[3]), "r"(b[0]), "r"(b[1]));
}

// ---------------- bf16x3 split-precision tensor-core GEMM ----------------
// C = A @ B (+bias)(+res / gelu / causal-scale), A = Ahi+Alo, B = Bhi+Blo.
// EPI: 0=bias, 1=bias+residual, 2=bias+gelu, 3=scale+causal mask (fp32 out)
// TB : B gmem [N,K] row-major; else [K,N]
// HILO: epilogue writes Ch/Cl bf16 pair instead of fp32 C
// Block tile 128 x BN x 32; 8 warps = 2(m) x 4(n).
template <int EPI, bool TB, int BN, bool HILO>
__global__ void __launch_bounds__(256)
gemm_bf3(const bf16* __restrict__ Ah, const bf16* __restrict__ Al,
         const bf16* __restrict__ Bh, const bf16* __restrict__ Bl,
         const float* __restrict__ bias, const float* __restrict__ res,
         float* __restrict__ C, bf16* __restrict__ Ch, bf16* __restrict__ Cl,
         int N, int K, int lda, int ldb, int ldc,
         long az, long bz, long cz) {
    constexpr int WN = BN / 4;       // warp n extent
    constexpr int NA = WN / 8;       // n atoms per warp
    constexpr int NP = NA / 2;       // ldmatrix.x4 pairs
    constexpr int LDA = 40;          // A smem row stride (bf16)
    constexpr int AHALF = 128 * LDA;
    constexpr int LDBN = BN + 8;     // non-TB B smem row stride
    constexpr int BSZ = TB ? BN * 40 : 32 * LDBN;
    constexpr int BOFF = 2 * AHALF;
    constexpr int STG = 2 * AHALF + 2 * BSZ;   // bf16 per stage

    extern __shared__ bf16 smem_[];
    uint32_t sb = (uint32_t)__cvta_generic_to_shared(smem_);

    int z = blockIdx.z;
    Ah += (long)z * az; Al += (long)z * az;
    Bh += (long)z * bz; Bl += (long)z * bz;
    if (HILO) { Ch += (long)z * cz; Cl += (long)z * cz; }
    else      { C  += (long)z * cz; }

    int m0 = blockIdx.y * 128;
    int n0 = blockIdx.x * BN;
    int tid = threadIdx.x, lane = tid & 31, wid = tid >> 5;
    int wm = wid & 1, wn = wid >> 1;
    int g = lane >> 2, qi = lane & 3;

    float acc[4][NA][4];
#pragma unroll
    for (int i = 0; i < 4; i++)
#pragma unroll
        for (int j = 0; j < NA; j++)
#pragma unroll
            for (int u = 0; u < 4; u++) acc[i][j][u] = 0.f;

    auto load_tile = [&](int kt, int s) {
        int k0 = kt * 32;
        uint32_t stg = sb + (uint32_t)(s * STG * 2);
        // A: 128 rows x 32 bf16 x {hi,lo} = 1024 16B chunks
#pragma unroll
        for (int j = 0; j < 4; j++) {
            int fid = tid + j * 256;
            int arr = fid >> 9;
            int row = (fid >> 2) & 127;
            int cc  = fid & 3;
            uint32_t dst = stg + (uint32_t)((arr * AHALF + row * LDA + cc * 8) * 2);
            const bf16* src = (arr ? Al : Ah) + (long)(m0 + row) * lda + k0 + cc * 8;
            CPA16(dst, src, 16);
        }
        if (TB) {
#pragma unroll
            for (int j = 0; j < BN / 32; j++) {
                int fid = tid + j * 256;
                int arr = fid >> 9;
                int row = (fid >> 2) & 127;
                int cc  = fid & 3;
                int n = n0 + row;
                int ok = (n < N) ? 16 : 0;
                int nc = (n < N) ? n : (N - 1);
                uint32_t dst = stg + (uint32_t)((BOFF + arr * BSZ + row * 40 + cc * 8) * 2);
                const bf16* src = (arr ? Bl : Bh) + (long)nc * ldb + k0 + cc * 8;
                CPA16(dst, src, ok);
            }
        } else {
            constexpr int CPR = BN / 8;           // chunks per k-row
            constexpr int TOT = 32 * CPR * 2;     // total chunks
#pragma unroll
            for (int j = 0; j < TOT / 256; j++) {
                int fid = tid + j * 256;
                int arr = fid / (32 * CPR);
                int rem = fid % (32 * CPR);
                int row = rem / CPR;
                int cc  = rem % CPR;
                uint32_t dst = stg + (uint32_t)((BOFF + arr * BSZ + row * LDBN + cc * 8) * 2);
                const bf16* src = (arr ? Bl : Bh) + (long)(k0 + row) * ldb + n0 + cc * 8;
                CPA16(dst, src, 16);
            }
        }
        asm volatile("cp.async.commit_group;\n");
    };

    int KT = K / 32;
    load_tile(0, 0);

    // lane-invariant fragment offsets
    int arow = wm * 64 + (lane & 15);
    int acolh = (lane & 16) ? 8 : 0;
    int tb_row = wn * WN + (lane & 7) + ((lane & 16) ? 8 : 0);
    int tb_colh = (lane & 8) ? 8 : 0;
    int nt_rowk = (lane & 15);
    int nt_col = wn * WN + ((lane & 16) ? 8 : 0);

    for (int kt = 0; kt < KT; kt++) {
        int s = kt & 1;
        if (kt + 1 < KT) {
            load_tile(kt + 1, s ^ 1);
            asm volatile("cp.async.wait_group 1;\n");
        } else {
            asm volatile("cp.async.wait_group 0;\n");
        }
        __syncthreads();

        uint32_t stg = sb + (uint32_t)(s * STG * 2);

#pragma unroll
        for (int ks = 0; ks < 2; ks++) {
            uint32_t ah[4][4], al[4][4];
#pragma unroll
            for (int ma = 0; ma < 4; ma++) {
                uint32_t ad = stg + (uint32_t)((((arow + ma * 16) * LDA) + ks * 16 + acolh) * 2);
                ldsm4(ah[ma][0], ah[ma][1], ah[ma][2], ah[ma][3], ad);
                ldsm4(al[ma][0], al[ma][1], al[ma][2], al[ma][3], ad + AHALF * 2);
            }
            uint32_t bh[NA][2], bl[NA][2];
#pragma unroll
            for (int p = 0; p < NP; p++) {
                if (TB) {
                    uint32_t bd = stg + (uint32_t)((BOFF + (tb_row + p * 16) * 40 + ks * 16 + tb_colh) * 2);
                    ldsm4(bh[2 * p][0], bh[2 * p][1], bh[2 * p + 1][0], bh[2 * p + 1][1], bd);
                    ldsm4(bl[2 * p][0], bl[2 * p][1], bl[2 * p + 1][0], bl[2 * p + 1][1], bd + BSZ * 2);
                } else {
                    uint32_t bd = stg + (uint32_t)((BOFF + (ks * 16 + nt_rowk) * LDBN + nt_col + p * 16) * 2);
                    ldsm4t(bh[2 * p][0], bh[2 * p][1], bh[2 * p + 1][0], bh[2 * p + 1][1], bd);
                    ldsm4t(bl[2 * p][0], bl[2 * p][1], bl[2 * p + 1][0], bl[2 * p + 1][1], bd + BSZ * 2);
                }
            }
#pragma unroll
            for (int ma = 0; ma < 4; ma++)
#pragma unroll
                for (int nb = 0; nb < NA; nb++) {
                    mma16816(acc[ma][nb], ah[ma], bh[nb]);
                    mma16816(acc[ma][nb], ah[ma], bl[nb]);
                    mma16816(acc[ma][nb], al[ma], bh[nb]);
                }
        }
        __syncthreads();
    }

    // ---------------- epilogue ----------------
#pragma unroll
    for (int ma = 0; ma < 4; ma++) {
        int r0 = m0 + wm * 64 + ma * 16 + g;
#pragma unroll
        for (int nb = 0; nb < NA; nb++) {
            int c0 = n0 + wn * WN + nb * 8 + 2 * qi;
#pragma unroll
            for (int hf = 0; hf < 2; hf++) {
                int r = r0 + hf * 8;
                float v0 = acc[ma][nb][hf * 2 + 0];
                float v1 = acc[ma][nb][hf * 2 + 1];
                if (EPI == 3) {
                    v0 *= 0.125f; v1 *= 0.125f;
                    if (c0 > r)     v0 = -INFINITY;
                    if (c0 + 1 > r) v1 = -INFINITY;
                    C[(long)r * ldc + c0]     = v0;
                    C[(long)r * ldc + c0 + 1] = v1;
                } else {
                    if (bias) { v0 += bias[c0]; v1 += bias[c0 + 1]; }
                    if (EPI == 1) {
                        v0 += res[(long)r * ldc + c0];
                        v1 += res[(long)r * ldc + c0 + 1];
                    }
                    if (EPI == 2) { v0 = gelu_f(v0); v1 = gelu_f(v1); }
                    if (HILO) {
                        bf16 h0, l0, h1, l1;
                        split_bf(v0, h0, l0); split_bf(v1, h1, l1);
                        bf162 hv; hv.x = h0; hv.y = h1;
                        bf162 lv; lv.x = l0; lv.y = l1;
                        *(bf162*)(Ch + (long)r * ldc + c0) = hv;
                        *(bf162*)(Cl + (long)r * ldc + c0) = lv;
                    } else {
                        if (c0 < N)     C[(long)r * ldc + c0]     = v0;
                        if (c0 + 1 < N) C[(long)r * ldc + c0 + 1] = v1;
                    }
                }
            }
        }
    }
}

// ---------------- launch helper ----------------
template <int EPI, bool TB, int BN, bool HILO>
static inline void launch_gemm(dim3 grid,
                               const bf16* Ah, const bf16* Al,
                               const bf16* Bh, const bf16* Bl,
                               const float* bias, const float* res,
                               float* C, bf16* Ch, bf16* Cl,
                               int N, int K, int lda, int ldb, int ldc,
                               long az, long bz, long cz) {
    constexpr int LDBN = BN + 8;
    constexpr int BSZ = TB ? BN * 40 : 32 * LDBN;
    constexpr int STG = 2 * 128 * 40 + 2 * BSZ;
    constexpr int BYTES = STG * 2 * 2;
    cudaFuncSetAttribute(gemm_bf3<EPI, TB, BN, HILO>,
                         cudaFuncAttributeMaxDynamicSharedMemorySize, BYTES);
    gemm_bf3<EPI, TB, BN, HILO><<<grid, 256, BYTES>>>(
        Ah, Al, Bh, Bl, bias, res, C, Ch, Cl, N, K, lda, ldb, ldc, az, bz, cz);
}

static inline void convert_w(const float* src, bf16* hi, bf16* lo, long n) {
    long n4 = n / 4;
    f2bf_kernel<<<(unsigned)((n4 + 255) / 256), 256>>>(
        (const float4*)src, (bf162*)hi, (bf162*)lo, n4);
}

// ---------------- host launcher ----------------
extern "C" void kernel_launch(void* const* d_in, const int* in_sizes, int n_in,
                              void* d_out, int out_size) {
    const int*   ids    = (const int*)d_in[0];
    const int*   sp     = (const int*)d_in[1];
    // d_in[2..4]: block table / kv pools — identity at start_pos=0, pools input-only.
    const float* wte    = (const float*)d_in[5];
    const float* wpe    = (const float*)d_in[6];
    const float* ln1_g  = (const float*)d_in[7];
    const float* ln1_b  = (const float*)d_in[8];
    const float* attn_w = (const float*)d_in[9];
    const float* attn_b = (const float*)d_in[10];
    const float* attn_pw= (const float*)d_in[11];
    const float* attn_pb= (const float*)d_in[12];
    const float* ln2_g  = (const float*)d_in[13];
    const float* ln2_b  = (const float*)d_in[14];
    const float* fc_w   = (const float*)d_in[15];
    const float* fc_b   = (const float*)d_in[16];
    const float* proj_w = (const float*)d_in[17];
    const float* proj_b = (const float*)d_in[18];
    const float* lnf_g  = (const float*)d_in[19];
    const float* lnf_b  = (const float*)d_in[20];
    float* out = (float*)d_out;

    float *x, *sc;
    bf16 *hh, *hl, *qh, *ql, *ath, *atl, *fh, *fl, *sph, *spl;
    bf16 *wqh, *wql, *wph, *wpl, *wfh, *wfl, *wjh, *wjl, *wth, *wtl;
    cudaGetSymbolAddress((void**)&x,   g_x);
    cudaGetSymbolAddress((void**)&sc,  g_sc);
    cudaGetSymbolAddress((void**)&hh,  g_h_hi);   cudaGetSymbolAddress((void**)&hl,  g_h_lo);
    cudaGetSymbolAddress((void**)&qh,  g_qkv_hi); cudaGetSymbolAddress((void**)&ql,  g_qkv_lo);
    cudaGetSymbolAddress((void**)&ath, g_attn_hi);cudaGetSymbolAddress((void**)&atl, g_attn_lo);
    cudaGetSymbolAddress((void**)&fh,  g_fc_hi);  cudaGetSymbolAddress((void**)&fl,  g_fc_lo);
    cudaGetSymbolAddress((void**)&sph, g_sp_hi);  cudaGetSymbolAddress((void**)&spl, g_sp_lo);
    cudaGetSymbolAddress((void**)&wqh, w_qkv_hi); cudaGetSymbolAddress((void**)&wql, w_qkv_lo);
    cudaGetSymbolAddress((void**)&wph, w_pw_hi);  cudaGetSymbolAddress((void**)&wpl, w_pw_lo);
    cudaGetSymbolAddress((void**)&wfh, w_fc_hi);  cudaGetSymbolAddress((void**)&wfl, w_fc_lo);
    cudaGetSymbolAddress((void**)&wjh, w_pj_hi);  cudaGetSymbolAddress((void**)&wjl, w_pj_lo);
    cudaGetSymbolAddress((void**)&wth, w_te_hi);  cudaGetSymbolAddress((void**)&wtl, w_te_lo);

    const int D = DMODEL;

    // per-call weight conversion to hi/lo bf16
    convert_w(attn_w,  wqh, wql, (long)NLAYER * D * 3 * D);
    convert_w(attn_pw, wph, wpl, (long)NLAYER * D * D);
    convert_w(fc_w,    wfh, wfl, (long)NLAYER * D * 4 * D);
    convert_w(proj_w,  wjh, wjl, (long)NLAYER * 4 * D * D);
    convert_w(wte,     wth, wtl, (long)VOCAB * D);

    embed_kernel<<<LSEQ, 256>>>(ids, sp, wte, wpe);

    for (int i = 0; i < NLAYER; i++) {
        ln_kernel<<<LSEQ, 256>>>(x, hh, hl, ln1_g + i * D, ln1_b + i * D);

        // qkv = h @ attn_w[i] + b  -> hi/lo   [1024, 2304]
        launch_gemm<0, false, 128, true>(dim3(18, 8, 1),
            hh, hl, wqh + (long)i * D * 3 * D, wql + (long)i * D * 3 * D,
            attn_b + (long)i * 3 * D, nullptr, nullptr, qh, ql,
            3 * D, D, D, 3 * D, 3 * D, 0, 0, 0);

        // scores = scale * Q Kᵀ (causal) -> fp32, batched over heads
        launch_gemm<3, true, 128, false>(dim3(8, 8, NHEAD),
            qh, ql, qh + D, ql + D, nullptr, nullptr, sc, nullptr, nullptr,
            LSEQ, HDIM, 3 * D, 3 * D, LSEQ,
            HDIM, HDIM, (long)LSEQ * LSEQ);

        softmax_kernel<<<NHEAD * LSEQ, 256>>>();

        // attn = P @ V -> hi/lo, batched over heads
        launch_gemm<0, false, 64, true>(dim3(1, 8, NHEAD),
            sph, spl, qh + 2 * D, ql + 2 * D, nullptr, nullptr,
            nullptr, ath, atl,
            HDIM, LSEQ, LSEQ, 3 * D, D,
            (long)LSEQ * LSEQ, HDIM, HDIM);

        // x = x + attn @ pw + pb  (fp32 residual)
        launch_gemm<1, false, 64, false>(dim3(12, 8, 1),
            ath, atl, wph + (long)i * D * D, wpl + (long)i * D * D,
            attn_pb + (long)i * D, x, x, nullptr, nullptr,
            D, D, D, D, D, 0, 0, 0);

        ln_kernel<<<LSEQ, 256>>>(x, hh, hl, ln2_g + i * D, ln2_b + i * D);

        // fc = gelu(h @ fc_w + b) -> hi/lo  [1024, 3072]
        launch_gemm<2, false, 128, true>(dim3(24, 8, 1),
            hh, hl, wfh + (long)i * D * 4 * D, wfl + (long)i * D * 4 * D,
            fc_b + (long)i * 4 * D, nullptr, nullptr, fh, fl,
            4 * D, D, D, 4 * D, 4 * D, 0, 0, 0);

        // x = x + fc @ proj_w + pb (fp32 residual)
        launch_gemm<1, false, 64, false>(dim3(12, 8, 1),
            fh, fl, wjh + (long)i * 4 * D * D, wjl + (long)i * 4 * D * D,
            proj_b + (long)i * D, x, x, nullptr, nullptr,
            D, 4 * D, 4 * D, D, D, 0, 0, 0);
    }

    // lnf + logits = h @ wteᵀ  [1024, 50257]
    ln_kernel<<<LSEQ, 256>>>(x, hh, hl, lnf_g, lnf_b);
    launch_gemm<0, true, 128, false>(dim3((VOCAB + 127) / 128, 8, 1),
        hh, hl, wth, wtl, nullptr, nullptr, out, nullptr, nullptr,
        VOCAB, D, D, D, VOCAB, 0, 0, 0);
}

// round 4
// speedup vs baseline: 2.6971x; 1.1531x over previous
#include <cuda_runtime.h>
#include <cuda_bf16.h>
#include <math.h>
#include <stdint.h>

#define LSEQ 1024
#define DMODEL 768
#define NHEAD 12
#define HDIM 64
#define NLAYER 12
#define VOCAB 50257

typedef __nv_bfloat16 bf16;
typedef __nv_bfloat162 bf162;

// ---------------- scratch (device globals; no allocation) ----------------
__device__ float g_x[LSEQ * DMODEL];                 // residual stream (fp32)
__device__ bf16  g_h_hi[LSEQ * DMODEL],  g_h_lo[LSEQ * DMODEL];
__device__ bf16  g_qkv_hi[LSEQ * 3 * DMODEL], g_qkv_lo[LSEQ * 3 * DMODEL];
__device__ bf16  g_attn_hi[LSEQ * DMODEL], g_attn_lo[LSEQ * DMODEL];
__device__ bf16  g_fc_hi[LSEQ * 4 * DMODEL], g_fc_lo[LSEQ * 4 * DMODEL];

// pre-converted weights (hi/lo bf16)
__device__ bf16 w_qkv_hi[NLAYER * DMODEL * 3 * DMODEL], w_qkv_lo[NLAYER * DMODEL * 3 * DMODEL];
__device__ bf16 w_pw_hi [NLAYER * DMODEL * DMODEL],     w_pw_lo [NLAYER * DMODEL * DMODEL];
__device__ bf16 w_fc_hi [NLAYER * DMODEL * 4 * DMODEL], w_fc_lo [NLAYER * DMODEL * 4 * DMODEL];
__device__ bf16 w_pj_hi [NLAYER * 4 * DMODEL * DMODEL], w_pj_lo [NLAYER * 4 * DMODEL * DMODEL];
__device__ bf16 w_te_hi [(long)VOCAB * DMODEL],         w_te_lo [(long)VOCAB * DMODEL];

// ---------------- helpers ----------------
__device__ __forceinline__ void split_bf(float v, bf16& h, bf16& l) {
    h = __float2bfloat16(v);
    l = __float2bfloat16(v - __bfloat162float(h));
}
__device__ __forceinline__ uint32_t pack_hilo(float x, float y, uint32_t& lo) {
    bf162 h = __float22bfloat162_rn(make_float2(x, y));
    float rx = x - __bfloat162float(h.x);
    float ry = y - __bfloat162float(h.y);
    bf162 l = __float22bfloat162_rn(make_float2(rx, ry));
    lo = *(uint32_t*)&l;
    return *(uint32_t*)&h;
}

// ---------------- weight conversion (fp32 -> hi/lo bf16) ----------------
__global__ void f2bf_kernel(const float4* __restrict__ src,
                            bf162* __restrict__ hi, bf162* __restrict__ lo, long n4) {
    long i = (long)blockIdx.x * blockDim.x + threadIdx.x;
    if (i >= n4) return;
    float4 v = src[i];
    bf16 hx, lx, hy, ly, hz, lz, hw, lw;
    split_bf(v.x, hx, lx); split_bf(v.y, hy, ly);
    split_bf(v.z, hz, lz); split_bf(v.w, hw, lw);
    bf162 a; a.x = hx; a.y = hy;
    bf162 b; b.x = hz; b.y = hw;
    hi[i * 2] = a; hi[i * 2 + 1] = b;
    a.x = lx; a.y = ly; b.x = lz; b.y = lw;
    lo[i * 2] = a; lo[i * 2 + 1] = b;
}

// ---------------- embedding ----------------
__global__ void embed_kernel(const int* __restrict__ ids,
                             const int* __restrict__ start_pos,
                             const float* __restrict__ wte,
                             const float* __restrict__ wpe) {
    int l = blockIdx.x;
    const float* we = wte + (long)ids[l] * DMODEL;
    const float* pe = wpe + (long)(start_pos[0] + l) * DMODEL;
    float* xr = g_x + (long)l * DMODEL;
    for (int d = threadIdx.x; d < DMODEL; d += blockDim.x)
        xr[d] = we[d] + pe[d];
}

// ---------------- layernorm: fp32 in -> hi/lo bf16 out ----------------
__global__ void ln_kernel(const float* __restrict__ in,
                          bf16* __restrict__ oh, bf16* __restrict__ ol,
                          const float* __restrict__ g, const float* __restrict__ b) {
    int l = blockIdx.x;
    int t = threadIdx.x;
    const float* row = in + (long)l * DMODEL;
    __shared__ float r1[256], r2[256];
    float s = 0.f, s2 = 0.f;
    for (int d = t; d < DMODEL; d += 256) {
        float v = row[d];
        s += v; s2 += v * v;
    }
    r1[t] = s; r2[t] = s2;
    __syncthreads();
    for (int o = 128; o > 0; o >>= 1) {
        if (t < o) { r1[t] += r1[t + o]; r2[t] += r2[t + o]; }
        __syncthreads();
    }
    float mean = r1[0] * (1.f / DMODEL);
    float var  = r2[0] * (1.f / DMODEL) - mean * mean;
    float inv = rsqrtf(var + 1e-5f);
    for (int d = t; d < DMODEL; d += 256) {
        float v = (row[d] - mean) * inv * g[d] + b[d];
        bf16 h, lo2; split_bf(v, h, lo2);
        oh[(long)l * DMODEL + d] = h;
        ol[(long)l * DMODEL + d] = lo2;
    }
}

__device__ __forceinline__ float gelu_f(float v) {
    float c = 0.7978845608028654f * (v + 0.044715f * v * v * v);
    return 0.5f * v * (1.f + tanhf(c));
}

#define CPA16(dst, src, sz) \
    asm volatile("cp.async.cg.shared.global [%0], [%1], 16, %2;\n" \
                 :: "r"(dst), "l"(src), "r"(sz))

__device__ __forceinline__ void ldsm4(uint32_t& r0, uint32_t& r1, uint32_t& r2, uint32_t& r3,
                                      uint32_t addr) {
    asm volatile("ldmatrix.sync.aligned.m8n8.x4.shared.b16 {%0,%1,%2,%3}, [%4];"
                 : "=r"(r0), "=r"(r1), "=r"(r2), "=r"(r3) : "r"(addr));
}
__device__ __forceinline__ void ldsm4t(uint32_t& r0, uint32_t& r1, uint32_t& r2, uint32_t& r3,
                                       uint32_t addr) {
    asm volatile("ldmatrix.sync.aligned.m8n8.x4.trans.shared.b16 {%0,%1,%2,%3}, [%4];"
                 : "=r"(r0), "=r"(r1), "=r"(r2), "=r"(r3) : "r"(addr));
}
__device__ __forceinline__ void mma16816(float* c, const uint32_t* a, const uint32_t* b) {
    asm volatile(
        "mma.sync.aligned.m16n8k16.row.col.f32.bf16.bf16.f32 "
        "{%0,%1,%2,%3}, {%4,%5,%6,%7}, {%8,%9}, {%0,%1,%2,%3};\n"
        : "+f"(c[0]), "+f"(c[1]), "+f"(c[2]), "+f"(c[3])
        : "r"(a[0]), "r"(a[1]), "r"(a[2]), "r"(a[3]), "r"(b[0]), "r"(b[1]));
}

// ---------------- fused flash attention ----------------
// grid (LSEQ/64, NHEAD), 128 threads (4 warps, 16 q-rows each).
// K/V hi/lo 64x64 tiles in smem; Q fragments in registers; online softmax.
__global__ void __launch_bounds__(128)
flash_kernel(const bf16* __restrict__ qkvh, const bf16* __restrict__ qkvl,
             bf16* __restrict__ outh, bf16* __restrict__ outl) {
    constexpr int FS = 72;
    constexpr int HALF = 64 * FS;
    __shared__ bf16 sm[4 * HALF];   // [KH][KL][VH][VL] (Q staged in KH/KL first)
    int qt = blockIdx.x, hd = blockIdx.y;
    int tid = threadIdx.x, lane = tid & 31, w = tid >> 5;
    int g = lane >> 2, qi = lane & 3;
    const int lda = 3 * DMODEL;
    uint32_t sb = (uint32_t)__cvta_generic_to_shared(sm);

    // ---- stage Q tile (hi/lo) and extract A fragments ----
#pragma unroll
    for (int i = 0; i < 8; i++) {
        int c = tid + i * 128;
        int arr = c >> 9, rem = c & 511, row = rem >> 3, cc = rem & 7;
        uint32_t dst = sb + (uint32_t)((arr * HALF + row * FS + cc * 8) * 2);
        const bf16* src = (arr ? qkvl : qkvh) + (long)(qt * 64 + row) * lda + hd * 64 + cc * 8;
        CPA16(dst, src, 16);
    }
    asm volatile("cp.async.commit_group;\n");
    asm volatile("cp.async.wait_group 0;\n");
    __syncthreads();

    uint32_t qfh[4][4], qfl[4][4];
    {
        int arow = w * 16 + (lane & 15);
        int acol = (lane & 16) ? 8 : 0;
#pragma unroll
        for (int kc = 0; kc < 4; kc++) {
            uint32_t ad = sb + (uint32_t)((arow * FS + kc * 16 + acol) * 2);
            ldsm4(qfh[kc][0], qfh[kc][1], qfh[kc][2], qfh[kc][3], ad);
            ldsm4(qfl[kc][0], qfl[kc][1], qfl[kc][2], qfl[kc][3], ad + HALF * 2);
        }
    }

    float o[8][4];
#pragma unroll
    for (int j = 0; j < 8; j++)
#pragma unroll
        for (int u = 0; u < 4; u++) o[j][u] = 0.f;
    float m0 = -1e30f, m1 = -1e30f, l0 = 0.f, l1 = 0.f;

    int rloc0 = w * 16 + g, rloc1 = rloc0 + 8;
    int krow = (lane & 7) + ((lane & 16) ? 8 : 0);
    int kcol = (lane & 8) ? 8 : 0;
    int vr   = lane & 15;
    int vch  = (lane & 16) ? 8 : 0;

    for (int kt = 0; kt <= qt; kt++) {
        __syncthreads();   // prior smem reads done
#pragma unroll
        for (int i = 0; i < 16; i++) {
            int c = tid + i * 128;
            int arr = c >> 9, rem = c & 511, row = rem >> 3, cc = rem & 7;
            const bf16* base = (arr & 1) ? qkvl : qkvh;
            int coloff = (arr & 2) ? 2 * DMODEL : DMODEL;   // V : K
            uint32_t dst = sb + (uint32_t)((arr * HALF + row * FS + cc * 8) * 2);
            const bf16* src = base + (long)(kt * 64 + row) * lda + coloff + hd * 64 + cc * 8;
            CPA16(dst, src, 16);
        }
        asm volatile("cp.async.commit_group;\n");
        asm volatile("cp.async.wait_group 0;\n");
        __syncthreads();

        // ---- scores = Q @ K^T (bf16x3) ----
        float s[8][4];
#pragma unroll
        for (int j = 0; j < 8; j++)
#pragma unroll
            for (int u = 0; u < 4; u++) s[j][u] = 0.f;

#pragma unroll
        for (int ks = 0; ks < 4; ks++) {
#pragma unroll
            for (int p = 0; p < 4; p++) {
                uint32_t bd = sb + (uint32_t)(((krow + p * 16) * FS + ks * 16 + kcol) * 2);
                uint32_t kh[4], kl[4];
                ldsm4(kh[0], kh[1], kh[2], kh[3], bd);
                ldsm4(kl[0], kl[1], kl[2], kl[3], bd + HALF * 2);
                mma16816(s[2 * p],     qfh[ks], kh);
                mma16816(s[2 * p],     qfh[ks], kl);
                mma16816(s[2 * p],     qfl[ks], kh);
                mma16816(s[2 * p + 1], qfh[ks], kh + 2);
                mma16816(s[2 * p + 1], qfh[ks], kl + 2);
                mma16816(s[2 * p + 1], qfl[ks], kh + 2);
            }
        }

        // ---- scale, causal mask, online softmax ----
        bool diag = (kt == qt);
        float mx0 = -1e30f, mx1 = -1e30f;
#pragma unroll
        for (int j = 0; j < 8; j++) {
            int c0 = 8 * j + 2 * qi;
            s[j][0] *= 0.125f; s[j][1] *= 0.125f;
            s[j][2] *= 0.125f; s[j][3] *= 0.125f;
            if (diag) {
                if (c0     > rloc0) s[j][0] = -1e30f;
                if (c0 + 1 > rloc0) s[j][1] = -1e30f;
                if (c0     > rloc1) s[j][2] = -1e30f;
                if (c0 + 1 > rloc1) s[j][3] = -1e30f;
            }
            mx0 = fmaxf(mx0, fmaxf(s[j][0], s[j][1]));
            mx1 = fmaxf(mx1, fmaxf(s[j][2], s[j][3]));
        }
        mx0 = fmaxf(mx0, __shfl_xor_sync(0xffffffffu, mx0, 1));
        mx0 = fmaxf(mx0, __shfl_xor_sync(0xffffffffu, mx0, 2));
        mx1 = fmaxf(mx1, __shfl_xor_sync(0xffffffffu, mx1, 1));
        mx1 = fmaxf(mx1, __shfl_xor_sync(0xffffffffu, mx1, 2));
        float mn0 = fmaxf(m0, mx0), mn1 = fmaxf(m1, mx1);
        float f0 = __expf(m0 - mn0), f1 = __expf(m1 - mn1);
        m0 = mn0; m1 = mn1;

        float rs0 = 0.f, rs1 = 0.f;
        uint32_t ph[4][4], pl[4][4];
#pragma unroll
        for (int kc = 0; kc < 4; kc++) {
            float p00 = __expf(s[2 * kc][0] - mn0), p01 = __expf(s[2 * kc][1] - mn0);
            float p02 = __expf(s[2 * kc][2] - mn1), p03 = __expf(s[2 * kc][3] - mn1);
            float p10 = __expf(s[2 * kc + 1][0] - mn0), p11 = __expf(s[2 * kc + 1][1] - mn0);
            float p12 = __expf(s[2 * kc + 1][2] - mn1), p13 = __expf(s[2 * kc + 1][3] - mn1);
            rs0 += p00 + p01 + p10 + p11;
            rs1 += p02 + p03 + p12 + p13;
            ph[kc][0] = pack_hilo(p00, p01, pl[kc][0]);
            ph[kc][1] = pack_hilo(p02, p03, pl[kc][1]);
            ph[kc][2] = pack_hilo(p10, p11, pl[kc][2]);
            ph[kc][3] = pack_hilo(p12, p13, pl[kc][3]);
        }
        l0 = l0 * f0 + rs0;
        l1 = l1 * f1 + rs1;
#pragma unroll
        for (int j = 0; j < 8; j++) {
            o[j][0] *= f0; o[j][1] *= f0; o[j][2] *= f1; o[j][3] *= f1;
        }

        // ---- o += P @ V (bf16x3) ----
#pragma unroll
        for (int kc = 0; kc < 4; kc++) {
#pragma unroll
            for (int p = 0; p < 4; p++) {
                uint32_t bd = sb + (uint32_t)((2 * HALF + (kc * 16 + vr) * FS + vch + p * 16) * 2);
                uint32_t vh[4], vl[4];
                ldsm4t(vh[0], vh[1], vh[2], vh[3], bd);
                ldsm4t(vl[0], vl[1], vl[2], vl[3], bd + HALF * 2);
                mma16816(o[2 * p],     ph[kc], vh);
                mma16816(o[2 * p],     ph[kc], vl);
                mma16816(o[2 * p],     pl[kc], vh);
                mma16816(o[2 * p + 1], ph[kc], vh + 2);
                mma16816(o[2 * p + 1], ph[kc], vl + 2);
                mma16816(o[2 * p + 1], pl[kc], vh + 2);
            }
        }
    }

    // ---- finalize: divide by row sums, write hi/lo bf16 ----
    l0 += __shfl_xor_sync(0xffffffffu, l0, 1);
    l0 += __shfl_xor_sync(0xffffffffu, l0, 2);
    l1 += __shfl_xor_sync(0xffffffffu, l1, 1);
    l1 += __shfl_xor_sync(0xffffffffu, l1, 2);
    float il0 = 1.f / l0, il1 = 1.f / l1;
    int row0 = qt * 64 + w * 16 + g, row1 = row0 + 8;
#pragma unroll
    for (int j = 0; j < 8; j++) {
        int col = hd * 64 + 8 * j + 2 * qi;
        uint32_t lo0, hi0 = pack_hilo(o[j][0] * il0, o[j][1] * il0, lo0);
        *(uint32_t*)(outh + (long)row0 * DMODEL + col) = hi0;
        *(uint32_t*)(outl + (long)row0 * DMODEL + col) = lo0;
        uint32_t lo1, hi1 = pack_hilo(o[j][2] * il1, o[j][3] * il1, lo1);
        *(uint32_t*)(outh + (long)row1 * DMODEL + col) = hi1;
        *(uint32_t*)(outl + (long)row1 * DMODEL + col) = lo1;
    }
}

// ---------------- bf16x3 split-precision tensor-core GEMM ----------------
// (unchanged from round 3 except EPI=3 path removed)
template <int EPI, bool TB, int BN, bool HILO>
__global__ void __launch_bounds__(256)
gemm_bf3(const bf16* __restrict__ Ah, const bf16* __restrict__ Al,
         const bf16* __restrict__ Bh, const bf16* __restrict__ Bl,
         const float* __restrict__ bias, const float* __restrict__ res,
         float* __restrict__ C, bf16* __restrict__ Ch, bf16* __restrict__ Cl,
         int N, int K, int lda, int ldb, int ldc,
         long az, long bz, long cz) {
    constexpr int WN = BN / 4;
    constexpr int NA = WN / 8;
    constexpr int NP = NA / 2;
    constexpr int LDA = 40;
    constexpr int AHALF = 128 * LDA;
    constexpr int LDBN = BN + 8;
    constexpr int BSZ = TB ? BN * 40 : 32 * LDBN;
    constexpr int BOFF = 2 * AHALF;
    constexpr int STG = 2 * AHALF + 2 * BSZ;

    extern __shared__ bf16 smem_[];
    uint32_t sb = (uint32_t)__cvta_generic_to_shared(smem_);

    int z = blockIdx.z;
    Ah += (long)z * az; Al += (long)z * az;
    Bh += (long)z * bz; Bl += (long)z * bz;
    if (HILO) { Ch += (long)z * cz; Cl += (long)z * cz; }
    else      { C  += (long)z * cz; }

    int m0 = blockIdx.y * 128;
    int n0 = blockIdx.x * BN;
    int tid = threadIdx.x, lane = tid & 31, wid = tid >> 5;
    int wm = wid & 1, wn = wid >> 1;
    int g = lane >> 2, qi = lane & 3;

    float acc[4][NA][4];
#pragma unroll
    for (int i = 0; i < 4; i++)
#pragma unroll
        for (int j = 0; j < NA; j++)
#pragma unroll
            for (int u = 0; u < 4; u++) acc[i][j][u] = 0.f;

    auto load_tile = [&](int kt, int s) {
        int k0 = kt * 32;
        uint32_t stg = sb + (uint32_t)(s * STG * 2);
#pragma unroll
        for (int j = 0; j < 4; j++) {
            int fid = tid + j * 256;
            int arr = fid >> 9;
            int row = (fid >> 2) & 127;
            int cc  = fid & 3;
            uint32_t dst = stg + (uint32_t)((arr * AHALF + row * LDA + cc * 8) * 2);
            const bf16* src = (arr ? Al : Ah) + (long)(m0 + row) * lda + k0 + cc * 8;
            CPA16(dst, src, 16);
        }
        if (TB) {
#pragma unroll
            for (int j = 0; j < BN / 32; j++) {
                int fid = tid + j * 256;
                int arr = fid >> 9;
                int row = (fid >> 2) & 127;
                int cc  = fid & 3;
                int n = n0 + row;
                int ok = (n < N) ? 16 : 0;
                int nc = (n < N) ? n : (N - 1);
                uint32_t dst = stg + (uint32_t)((BOFF + arr * BSZ + row * 40 + cc * 8) * 2);
                const bf16* src = (arr ? Bl : Bh) + (long)nc * ldb + k0 + cc * 8;
                CPA16(dst, src, ok);
            }
        } else {
            constexpr int CPR = BN / 8;
            constexpr int TOT = 32 * CPR * 2;
#pragma unroll
            for (int j = 0; j < TOT / 256; j++) {
                int fid = tid + j * 256;
                int arr = fid / (32 * CPR);
                int rem = fid % (32 * CPR);
                int row = rem / CPR;
                int cc  = rem % CPR;
                uint32_t dst = stg + (uint32_t)((BOFF + arr * BSZ + row * LDBN + cc * 8) * 2);
                const bf16* src = (arr ? Bl : Bh) + (long)(k0 + row) * ldb + n0 + cc * 8;
                CPA16(dst, src, 16);
            }
        }
        asm volatile("cp.async.commit_group;\n");
    };

    int KT = K / 32;
    load_tile(0, 0);

    int arow = wm * 64 + (lane & 15);
    int acolh = (lane & 16) ? 8 : 0;
    int tb_row = wn * WN + (lane & 7) + ((lane & 16) ? 8 : 0);
    int tb_colh = (lane & 8) ? 8 : 0;
    int nt_rowk = (lane & 15);
    int nt_col = wn * WN + ((lane & 16) ? 8 : 0);

    for (int kt = 0; kt < KT; kt++) {
        int s = kt & 1;
        if (kt + 1 < KT) {
            load_tile(kt + 1, s ^ 1);
            asm volatile("cp.async.wait_group 1;\n");
        } else {
            asm volatile("cp.async.wait_group 0;\n");
        }
        __syncthreads();

        uint32_t stg = sb + (uint32_t)(s * STG * 2);

#pragma unroll
        for (int ks = 0; ks < 2; ks++) {
            uint32_t ah[4][4], al[4][4];
#pragma unroll
            for (int ma = 0; ma < 4; ma++) {
                uint32_t ad = stg + (uint32_t)((((arow + ma * 16) * LDA) + ks * 16 + acolh) * 2);
                ldsm4(ah[ma][0], ah[ma][1], ah[ma][2], ah[ma][3], ad);
                ldsm4(al[ma][0], al[ma][1], al[ma][2], al[ma][3], ad + AHALF * 2);
            }
            uint32_t bh[NA][2], bl[NA][2];
#pragma unroll
            for (int p = 0; p < NP; p++) {
                if (TB) {
                    uint32_t bd = stg + (uint32_t)((BOFF + (tb_row + p * 16) * 40 + ks * 16 + tb_colh) * 2);
                    ldsm4(bh[2 * p][0], bh[2 * p][1], bh[2 * p + 1][0], bh[2 * p + 1][1], bd);
                    ldsm4(bl[2 * p][0], bl[2 * p][1], bl[2 * p + 1][0], bl[2 * p + 1][1], bd + BSZ * 2);
                } else {
                    uint32_t bd = stg + (uint32_t)((BOFF + (ks * 16 + nt_rowk) * LDBN + nt_col + p * 16) * 2);
                    ldsm4t(bh[2 * p][0], bh[2 * p][1], bh[2 * p + 1][0], bh[2 * p + 1][1], bd);
                    ldsm4t(bl[2 * p][0], bl[2 * p][1], bl[2 * p + 1][0], bl[2 * p + 1][1], bd + BSZ * 2);
                }
            }
#pragma unroll
            for (int ma = 0; ma < 4; ma++)
#pragma unroll
                for (int nb = 0; nb < NA; nb++) {
                    mma16816(acc[ma][nb], ah[ma], bh[nb]);
                    mma16816(acc[ma][nb], ah[ma], bl[nb]);
                    mma16816(acc[ma][nb], al[ma], bh[nb]);
                }
        }
        __syncthreads();
    }

#pragma unroll
    for (int ma = 0; ma < 4; ma++) {
        int r0 = m0 + wm * 64 + ma * 16 + g;
#pragma unroll
        for (int nb = 0; nb < NA; nb++) {
            int c0 = n0 + wn * WN + nb * 8 + 2 * qi;
#pragma unroll
            for (int hf = 0; hf < 2; hf++) {
                int r = r0 + hf * 8;
                float v0 = acc[ma][nb][hf * 2 + 0];
                float v1 = acc[ma][nb][hf * 2 + 1];
                if (bias) { v0 += bias[c0]; v1 += bias[c0 + 1]; }
                if (EPI == 1) {
                    v0 += res[(long)r * ldc + c0];
                    v1 += res[(long)r * ldc + c0 + 1];
                }
                if (EPI == 2) { v0 = gelu_f(v0); v1 = gelu_f(v1); }
                if (HILO) {
                    bf16 h0, l0x, h1, l1x;
                    split_bf(v0, h0, l0x); split_bf(v1, h1, l1x);
                    bf162 hv; hv.x = h0; hv.y = h1;
                    bf162 lv; lv.x = l0x; lv.y = l1x;
                    *(bf162*)(Ch + (long)r * ldc + c0) = hv;
                    *(bf162*)(Cl + (long)r * ldc + c0) = lv;
                } else {
                    if (c0 < N)     C[(long)r * ldc + c0]     = v0;
                    if (c0 + 1 < N) C[(long)r * ldc + c0 + 1] = v1;
                }
            }
        }
    }
}

// ---------------- launch helper ----------------
template <int EPI, bool TB, int BN, bool HILO>
static inline void launch_gemm(dim3 grid,
                               const bf16* Ah, const bf16* Al,
                               const bf16* Bh, const bf16* Bl,
                               const float* bias, const float* res,
                               float* C, bf16* Ch, bf16* Cl,
                               int N, int K, int lda, int ldb, int ldc,
                               long az, long bz, long cz) {
    constexpr int LDBN = BN + 8;
    constexpr int BSZ = TB ? BN * 40 : 32 * LDBN;
    constexpr int STG = 2 * 128 * 40 + 2 * BSZ;
    constexpr int BYTES = STG * 2 * 2;
    cudaFuncSetAttribute(gemm_bf3<EPI, TB, BN, HILO>,
                         cudaFuncAttributeMaxDynamicSharedMemorySize, BYTES);
    gemm_bf3<EPI, TB, BN, HILO><<<grid, 256, BYTES>>>(
        Ah, Al, Bh, Bl, bias, res, C, Ch, Cl, N, K, lda, ldb, ldc, az, bz, cz);
}

static inline void convert_w(const float* src, bf16* hi, bf16* lo, long n) {
    long n4 = n / 4;
    f2bf_kernel<<<(unsigned)((n4 + 255) / 256), 256>>>(
        (const float4*)src, (bf162*)hi, (bf162*)lo, n4);
}

// ---------------- host launcher ----------------
extern "C" void kernel_launch(void* const* d_in, const int* in_sizes, int n_in,
                              void* d_out, int out_size) {
    const int*   ids    = (const int*)d_in[0];
    const int*   sp     = (const int*)d_in[1];
    // d_in[2..4]: block table / kv pools — identity at start_pos=0, pools input-only.
    const float* wte    = (const float*)d_in[5];
    const float* wpe    = (const float*)d_in[6];
    const float* ln1_g  = (const float*)d_in[7];
    const float* ln1_b  = (const float*)d_in[8];
    const float* attn_w = (const float*)d_in[9];
    const float* attn_b = (const float*)d_in[10];
    const float* attn_pw= (const float*)d_in[11];
    const float* attn_pb= (const float*)d_in[12];
    const float* ln2_g  = (const float*)d_in[13];
    const float* ln2_b  = (const float*)d_in[14];
    const float* fc_w   = (const float*)d_in[15];
    const float* fc_b   = (const float*)d_in[16];
    const float* proj_w = (const float*)d_in[17];
    const float* proj_b = (const float*)d_in[18];
    const float* lnf_g  = (const float*)d_in[19];
    const float* lnf_b  = (const float*)d_in[20];
    float* out = (float*)d_out;

    float *x;
    bf16 *hh, *hl, *qh, *ql, *ath, *atl, *fh, *fl;
    bf16 *wqh, *wql, *wph, *wpl, *wfh, *wfl, *wjh, *wjl, *wth, *wtl;
    cudaGetSymbolAddress((void**)&x,   g_x);
    cudaGetSymbolAddress((void**)&hh,  g_h_hi);   cudaGetSymbolAddress((void**)&hl,  g_h_lo);
    cudaGetSymbolAddress((void**)&qh,  g_qkv_hi); cudaGetSymbolAddress((void**)&ql,  g_qkv_lo);
    cudaGetSymbolAddress((void**)&ath, g_attn_hi);cudaGetSymbolAddress((void**)&atl, g_attn_lo);
    cudaGetSymbolAddress((void**)&fh,  g_fc_hi);  cudaGetSymbolAddress((void**)&fl,  g_fc_lo);
    cudaGetSymbolAddress((void**)&wqh, w_qkv_hi); cudaGetSymbolAddress((void**)&wql, w_qkv_lo);
    cudaGetSymbolAddress((void**)&wph, w_pw_hi);  cudaGetSymbolAddress((void**)&wpl, w_pw_lo);
    cudaGetSymbolAddress((void**)&wfh, w_fc_hi);  cudaGetSymbolAddress((void**)&wfl, w_fc_lo);
    cudaGetSymbolAddress((void**)&wjh, w_pj_hi);  cudaGetSymbolAddress((void**)&wjl, w_pj_lo);
    cudaGetSymbolAddress((void**)&wth, w_te_hi);  cudaGetSymbolAddress((void**)&wtl, w_te_lo);

    const int D = DMODEL;

    convert_w(attn_w,  wqh, wql, (long)NLAYER * D * 3 * D);
    convert_w(attn_pw, wph, wpl, (long)NLAYER * D * D);
    convert_w(fc_w,    wfh, wfl, (long)NLAYER * D * 4 * D);
    convert_w(proj_w,  wjh, wjl, (long)NLAYER * 4 * D * D);
    convert_w(wte,     wth, wtl, (long)VOCAB * D);

    embed_kernel<<<LSEQ, 256>>>(ids, sp, wte, wpe);

    for (int i = 0; i < NLAYER; i++) {
        ln_kernel<<<LSEQ, 256>>>(x, hh, hl, ln1_g + i * D, ln1_b + i * D);

        // qkv = h @ attn_w[i] + b  -> hi/lo   [1024, 2304]
        launch_gemm<0, false, 128, true>(dim3(18, 8, 1),
            hh, hl, wqh + (long)i * D * 3 * D, wql + (long)i * D * 3 * D,
            attn_b + (long)i * 3 * D, nullptr, nullptr, qh, ql,
            3 * D, D, D, 3 * D, 3 * D, 0, 0, 0);

        // fused flash attention -> attn hi/lo
        flash_kernel<<<dim3(LSEQ / 64, NHEAD), 128>>>(qh, ql, ath, atl);

        // x = x + attn @ pw + pb
        launch_gemm<1, false, 64, false>(dim3(12, 8, 1),
            ath, atl, wph + (long)i * D * D, wpl + (long)i * D * D,
            attn_pb + (long)i * D, x, x, nullptr, nullptr,
            D, D, D, D, D, 0, 0, 0);

        ln_kernel<<<LSEQ, 256>>>(x, hh, hl, ln2_g + i * D, ln2_b + i * D);

        // fc = gelu(h @ fc_w + b) -> hi/lo  [1024, 3072]
        launch_gemm<2, false, 128, true>(dim3(24, 8, 1),
            hh, hl, wfh + (long)i * D * 4 * D, wfl + (long)i * D * 4 * D,
            fc_b + (long)i * 4 * D, nullptr, nullptr, fh, fl,
            4 * D, D, D, 4 * D, 4 * D, 0, 0, 0);

        // x = x + fc @ proj_w + pb
        launch_gemm<1, false, 64, false>(dim3(12, 8, 1),
            fh, fl, wjh + (long)i * 4 * D * D, wjl + (long)i * 4 * D * D,
            proj_b + (long)i * D, x, x, nullptr, nullptr,
            D, 4 * D, 4 * D, D, D, 0, 0, 0);
    }

    // lnf + logits = h @ wteᵀ  [1024, 50257]
    ln_kernel<<<LSEQ, 256>>>(x, hh, hl, lnf_g, lnf_b);
    launch_gemm<0, true, 128, false>(dim3((VOCAB + 127) / 128, 8, 1),
        hh, hl, wth, wtl, nullptr, nullptr, out, nullptr, nullptr,
        VOCAB, D, D, D, VOCAB, 0, 0, 0);
}

// round 6
// speedup vs baseline: 3.1681x; 1.1746x over previous
#include <cuda_runtime.h>
#include <cuda_bf16.h>
#include <math.h>
#include <stdint.h>

#define LSEQ 1024
#define DMODEL 768
#define NHEAD 12
#define HDIM 64
#define NLAYER 12
#define VOCAB 50257

typedef __nv_bfloat16 bf16;
typedef __nv_bfloat162 bf162;

// ---------------- scratch (device globals; no allocation) ----------------
__device__ float g_x[LSEQ * DMODEL];                 // residual stream (fp32)
__device__ bf16  g_h_hi[LSEQ * DMODEL],  g_h_lo[LSEQ * DMODEL];
__device__ bf16  g_qkv_hi[LSEQ * 3 * DMODEL], g_qkv_lo[LSEQ * 3 * DMODEL];
__device__ bf16  g_attn_hi[LSEQ * DMODEL], g_attn_lo[LSEQ * DMODEL];
__device__ bf16  g_fc_hi[LSEQ * 4 * DMODEL], g_fc_lo[LSEQ * 4 * DMODEL];
__device__ float g_part[3 * LSEQ * DMODEL];          // split-K partials (fp32)

// pre-converted weights (hi/lo bf16), layout [K,N] as given
__device__ bf16 w_qkv_hi[NLAYER * DMODEL * 3 * DMODEL], w_qkv_lo[NLAYER * DMODEL * 3 * DMODEL];
__device__ bf16 w_pw_hi [NLAYER * DMODEL * DMODEL],     w_pw_lo [NLAYER * DMODEL * DMODEL];
__device__ bf16 w_fc_hi [NLAYER * DMODEL * 4 * DMODEL], w_fc_lo [NLAYER * DMODEL * 4 * DMODEL];
__device__ bf16 w_pj_hi [NLAYER * 4 * DMODEL * DMODEL], w_pj_lo [NLAYER * 4 * DMODEL * DMODEL];
__device__ bf16 w_te_hi [(long)VOCAB * DMODEL],         w_te_lo [(long)VOCAB * DMODEL];

// ---------------- helpers ----------------
__device__ __forceinline__ void split_bf(float v, bf16& h, bf16& l) {
    h = __float2bfloat16(v);
    l = __float2bfloat16(v - __bfloat162float(h));
}
__device__ __forceinline__ uint32_t pack_hilo(float x, float y, uint32_t& lo) {
    bf162 h = __float22bfloat162_rn(make_float2(x, y));
    float rx = x - __bfloat162float(h.x);
    float ry = y - __bfloat162float(h.y);
    bf162 l = __float22bfloat162_rn(make_float2(rx, ry));
    lo = *(uint32_t*)&l;
    return *(uint32_t*)&h;
}
__device__ __forceinline__ float gelu_f(float v) {
    float c = 0.7978845608028654f * (v + 0.044715f * v * v * v);
    return 0.5f * v * (1.f + tanhf(c));
}

// ---------------- weight conversion (fp32 -> hi/lo bf16) ----------------
__global__ void f2bf_kernel(const float4* __restrict__ src,
                            bf162* __restrict__ hi, bf162* __restrict__ lo, long n4) {
    long i = (long)blockIdx.x * blockDim.x + threadIdx.x;
    if (i >= n4) return;
    float4 v = src[i];
    bf16 hx, lx, hy, ly, hz, lz, hw, lw;
    split_bf(v.x, hx, lx); split_bf(v.y, hy, ly);
    split_bf(v.z, hz, lz); split_bf(v.w, hw, lw);
    bf162 a; a.x = hx; a.y = hy;
    bf162 b; b.x = hz; b.y = hw;
    hi[i * 2] = a; hi[i * 2 + 1] = b;
    a.x = lx; a.y = ly; b.x = lz; b.y = lw;
    lo[i * 2] = a; lo[i * 2 + 1] = b;
}

// ---------------- embedding ----------------
__global__ void embed_kernel(const int* __restrict__ ids,
                             const int* __restrict__ start_pos,
                             const float* __restrict__ wte,
                             const float* __restrict__ wpe) {
    int l = blockIdx.x;
    const float* we = wte + (long)ids[l] * DMODEL;
    const float* pe = wpe + (long)(start_pos[0] + l) * DMODEL;
    float* xr = g_x + (long)l * DMODEL;
    for (int d = threadIdx.x; d < DMODEL; d += blockDim.x)
        xr[d] = we[d] + pe[d];
}

// ---------------- layernorm: fp32 in -> hi/lo bf16 out ----------------
__global__ void ln_kernel(const float* __restrict__ in,
                          bf16* __restrict__ oh, bf16* __restrict__ ol,
                          const float* __restrict__ g, const float* __restrict__ b) {
    int l = blockIdx.x;
    int t = threadIdx.x;
    const float* row = in + (long)l * DMODEL;
    __shared__ float r1[256], r2[256];
    float s = 0.f, s2 = 0.f;
    for (int d = t; d < DMODEL; d += 256) {
        float v = row[d];
        s += v; s2 += v * v;
    }
    r1[t] = s; r2[t] = s2;
    __syncthreads();
    for (int o = 128; o > 0; o >>= 1) {
        if (t < o) { r1[t] += r1[t + o]; r2[t] += r2[t + o]; }
        __syncthreads();
    }
    float mean = r1[0] * (1.f / DMODEL);
    float var  = r2[0] * (1.f / DMODEL) - mean * mean;
    float inv = rsqrtf(var + 1e-5f);
    for (int d = t; d < DMODEL; d += 256) {
        float v = (row[d] - mean) * inv * g[d] + b[d];
        bf16 h, lo2; split_bf(v, h, lo2);
        oh[(long)l * DMODEL + d] = h;
        ol[(long)l * DMODEL + d] = lo2;
    }
}

// ---------------- fused split-K reduce + residual + next-LN ----------------
// x[r] += bias + p0[r]+p1[r]+p2[r]; then oh/ol = LN(x[r]) with (g,b).
// One block per row; 256 threads x 3 cols.
__global__ void __launch_bounds__(256)
reduce_ln_kernel(const float* __restrict__ part, const float* __restrict__ bias,
                 float* __restrict__ x,
                 const float* __restrict__ g, const float* __restrict__ b,
                 bf16* __restrict__ oh, bf16* __restrict__ ol) {
    constexpr long MN = (long)LSEQ * DMODEL;
    int r = blockIdx.x, t = threadIdx.x;
    long ro = (long)r * DMODEL;
    float v[3];
    float s = 0.f, s2 = 0.f;
#pragma unroll
    for (int i = 0; i < 3; i++) {
        int c = t + i * 256;
        float val = x[ro + c] + bias[c]
                  + part[ro + c] + part[MN + ro + c] + part[2 * MN + ro + c];
        v[i] = val;
        s += val; s2 += val * val;
    }
    __shared__ float r1[256], r2[256];
    r1[t] = s; r2[t] = s2;
    __syncthreads();
    for (int o = 128; o > 0; o >>= 1) {
        if (t < o) { r1[t] += r1[t + o]; r2[t] += r2[t + o]; }
        __syncthreads();
    }
    float mean = r1[0] * (1.f / DMODEL);
    float var  = r2[0] * (1.f / DMODEL) - mean * mean;
    float inv = rsqrtf(var + 1e-5f);
#pragma unroll
    for (int i = 0; i < 3; i++) {
        int c = t + i * 256;
        x[ro + c] = v[i];
        float lv = (v[i] - mean) * inv * g[c] + b[c];
        bf16 h, lo2; split_bf(lv, h, lo2);
        oh[ro + c] = h;
        ol[ro + c] = lo2;
    }
}

#define CPA16(dst, src, sz) \
    asm volatile("cp.async.cg.shared.global [%0], [%1], 16, %2;\n" \
                 :: "r"(dst), "l"(src), "r"(sz))

__device__ __forceinline__ void ldsm4(uint32_t& r0, uint32_t& r1, uint32_t& r2, uint32_t& r3,
                                      uint32_t addr) {
    asm volatile("ldmatrix.sync.aligned.m8n8.x4.shared.b16 {%0,%1,%2,%3}, [%4];"
                 : "=r"(r0), "=r"(r1), "=r"(r2), "=r"(r3) : "r"(addr));
}
__device__ __forceinline__ void ldsm4t(uint32_t& r0, uint32_t& r1, uint32_t& r2, uint32_t& r3,
                                       uint32_t addr) {
    asm volatile("ldmatrix.sync.aligned.m8n8.x4.trans.shared.b16 {%0,%1,%2,%3}, [%4];"
                 : "=r"(r0), "=r"(r1), "=r"(r2), "=r"(r3) : "r"(addr));
}
__device__ __forceinline__ void mma16816(float* c, const uint32_t* a, const uint32_t* b) {
    asm volatile(
        "mma.sync.aligned.m16n8k16.row.col.f32.bf16.bf16.f32 "
        "{%0,%1,%2,%3}, {%4,%5,%6,%7}, {%8,%9}, {%0,%1,%2,%3};\n"
        : "+f"(c[0]), "+f"(c[1]), "+f"(c[2]), "+f"(c[3])
        : "r"(a[0]), "r"(a[1]), "r"(a[2]), "r"(a[3]), "r"(b[0]), "r"(b[1]));
}

// ---------------- fused flash attention (round-4, q-tiles reversed) ----------------
__global__ void __launch_bounds__(128)
flash_kernel(const bf16* __restrict__ qkvh, const bf16* __restrict__ qkvl,
             bf16* __restrict__ outh, bf16* __restrict__ outl) {
    constexpr int FS = 72;
    constexpr int HALF = 64 * FS;
    __shared__ bf16 sm[4 * HALF];
    int qt = gridDim.x - 1 - blockIdx.x;     // longest blocks first
    int hd = blockIdx.y;
    int tid = threadIdx.x, lane = tid & 31, w = tid >> 5;
    int g = lane >> 2, qi = lane & 3;
    const int lda = 3 * DMODEL;
    uint32_t sb = (uint32_t)__cvta_generic_to_shared(sm);

#pragma unroll
    for (int i = 0; i < 8; i++) {
        int c = tid + i * 128;
        int arr = c >> 9, rem = c & 511, row = rem >> 3, cc = rem & 7;
        uint32_t dst = sb + (uint32_t)((arr * HALF + row * FS + cc * 8) * 2);
        const bf16* src = (arr ? qkvl : qkvh) + (long)(qt * 64 + row) * lda + hd * 64 + cc * 8;
        CPA16(dst, src, 16);
    }
    asm volatile("cp.async.commit_group;\n");
    asm volatile("cp.async.wait_group 0;\n");
    __syncthreads();

    uint32_t qfh[4][4], qfl[4][4];
    {
        int arow = w * 16 + (lane & 15);
        int acol = (lane & 16) ? 8 : 0;
#pragma unroll
        for (int kc = 0; kc < 4; kc++) {
            uint32_t ad = sb + (uint32_t)((arow * FS + kc * 16 + acol) * 2);
            ldsm4(qfh[kc][0], qfh[kc][1], qfh[kc][2], qfh[kc][3], ad);
            ldsm4(qfl[kc][0], qfl[kc][1], qfl[kc][2], qfl[kc][3], ad + HALF * 2);
        }
    }

    float o[8][4];
#pragma unroll
    for (int j = 0; j < 8; j++)
#pragma unroll
        for (int u = 0; u < 4; u++) o[j][u] = 0.f;
    float m0 = -1e30f, m1 = -1e30f, l0 = 0.f, l1 = 0.f;

    int rloc0 = w * 16 + g, rloc1 = rloc0 + 8;
    int krow = (lane & 7) + ((lane & 16) ? 8 : 0);
    int kcol = (lane & 8) ? 8 : 0;
    int vr   = lane & 15;
    int vch  = (lane & 16) ? 8 : 0;

    for (int kt = 0; kt <= qt; kt++) {
        __syncthreads();
#pragma unroll
        for (int i = 0; i < 16; i++) {
            int c = tid + i * 128;
            int arr = c >> 9, rem = c & 511, row = rem >> 3, cc = rem & 7;
            const bf16* base = (arr & 1) ? qkvl : qkvh;
            int coloff = (arr & 2) ? 2 * DMODEL : DMODEL;
            uint32_t dst = sb + (uint32_t)((arr * HALF + row * FS + cc * 8) * 2);
            const bf16* src = base + (long)(kt * 64 + row) * lda + coloff + hd * 64 + cc * 8;
            CPA16(dst, src, 16);
        }
        asm volatile("cp.async.commit_group;\n");
        asm volatile("cp.async.wait_group 0;\n");
        __syncthreads();

        float s[8][4];
#pragma unroll
        for (int j = 0; j < 8; j++)
#pragma unroll
            for (int u = 0; u < 4; u++) s[j][u] = 0.f;

#pragma unroll
        for (int ks = 0; ks < 4; ks++) {
#pragma unroll
            for (int p = 0; p < 4; p++) {
                uint32_t bd = sb + (uint32_t)(((krow + p * 16) * FS + ks * 16 + kcol) * 2);
                uint32_t kh[4], kl[4];
                ldsm4(kh[0], kh[1], kh[2], kh[3], bd);
                ldsm4(kl[0], kl[1], kl[2], kl[3], bd + HALF * 2);
                mma16816(s[2 * p],     qfh[ks], kh);
                mma16816(s[2 * p],     qfh[ks], kl);
                mma16816(s[2 * p],     qfl[ks], kh);
                mma16816(s[2 * p + 1], qfh[ks], kh + 2);
                mma16816(s[2 * p + 1], qfh[ks], kl + 2);
                mma16816(s[2 * p + 1], qfl[ks], kh + 2);
            }
        }

        bool diag = (kt == qt);
        float mx0 = -1e30f, mx1 = -1e30f;
#pragma unroll
        for (int j = 0; j < 8; j++) {
            int c0 = 8 * j + 2 * qi;
            s[j][0] *= 0.125f; s[j][1] *= 0.125f;
            s[j][2] *= 0.125f; s[j][3] *= 0.125f;
            if (diag) {
                if (c0     > rloc0) s[j][0] = -1e30f;
                if (c0 + 1 > rloc0) s[j][1] = -1e30f;
                if (c0     > rloc1) s[j][2] = -1e30f;
                if (c0 + 1 > rloc1) s[j][3] = -1e30f;
            }
            mx0 = fmaxf(mx0, fmaxf(s[j][0], s[j][1]));
            mx1 = fmaxf(mx1, fmaxf(s[j][2], s[j][3]));
        }
        mx0 = fmaxf(mx0, __shfl_xor_sync(0xffffffffu, mx0, 1));
        mx0 = fmaxf(mx0, __shfl_xor_sync(0xffffffffu, mx0, 2));
        mx1 = fmaxf(mx1, __shfl_xor_sync(0xffffffffu, mx1, 1));
        mx1 = fmaxf(mx1, __shfl_xor_sync(0xffffffffu, mx1, 2));
        float mn0 = fmaxf(m0, mx0), mn1 = fmaxf(m1, mx1);
        float f0 = __expf(m0 - mn0), f1 = __expf(m1 - mn1);
        m0 = mn0; m1 = mn1;

        float rs0 = 0.f, rs1 = 0.f;
        uint32_t ph[4][4], pl[4][4];
#pragma unroll
        for (int kc = 0; kc < 4; kc++) {
            float p00 = __expf(s[2 * kc][0] - mn0), p01 = __expf(s[2 * kc][1] - mn0);
            float p02 = __expf(s[2 * kc][2] - mn1), p03 = __expf(s[2 * kc][3] - mn1);
            float p10 = __expf(s[2 * kc + 1][0] - mn0), p11 = __expf(s[2 * kc + 1][1] - mn0);
            float p12 = __expf(s[2 * kc + 1][2] - mn1), p13 = __expf(s[2 * kc + 1][3] - mn1);
            rs0 += p00 + p01 + p10 + p11;
            rs1 += p02 + p03 + p12 + p13;
            ph[kc][0] = pack_hilo(p00, p01, pl[kc][0]);
            ph[kc][1] = pack_hilo(p02, p03, pl[kc][1]);
            ph[kc][2] = pack_hilo(p10, p11, pl[kc][2]);
            ph[kc][3] = pack_hilo(p12, p13, pl[kc][3]);
        }
        l0 = l0 * f0 + rs0;
        l1 = l1 * f1 + rs1;
#pragma unroll
        for (int j = 0; j < 8; j++) {
            o[j][0] *= f0; o[j][1] *= f0; o[j][2] *= f1; o[j][3] *= f1;
        }

#pragma unroll
        for (int kc = 0; kc < 4; kc++) {
#pragma unroll
            for (int p = 0; p < 4; p++) {
                uint32_t bd = sb + (uint32_t)((2 * HALF + (kc * 16 + vr) * FS + vch + p * 16) * 2);
                uint32_t vh[4], vl[4];
                ldsm4t(vh[0], vh[1], vh[2], vh[3], bd);
                ldsm4t(vl[0], vl[1], vl[2], vl[3], bd + HALF * 2);
                mma16816(o[2 * p],     ph[kc], vh);
                mma16816(o[2 * p],     ph[kc], vl);
                mma16816(o[2 * p],     pl[kc], vh);
                mma16816(o[2 * p + 1], ph[kc], vh + 2);
                mma16816(o[2 * p + 1], ph[kc], vl + 2);
                mma16816(o[2 * p + 1], pl[kc], vh + 2);
            }
        }
    }

    l0 += __shfl_xor_sync(0xffffffffu, l0, 1);
    l0 += __shfl_xor_sync(0xffffffffu, l0, 2);
    l1 += __shfl_xor_sync(0xffffffffu, l1, 1);
    l1 += __shfl_xor_sync(0xffffffffu, l1, 2);
    float il0 = 1.f / l0, il1 = 1.f / l1;
    int row0 = qt * 64 + w * 16 + g, row1 = row0 + 8;
#pragma unroll
    for (int j = 0; j < 8; j++) {
        int col = hd * 64 + 8 * j + 2 * qi;
        uint32_t lo0, hi0 = pack_hilo(o[j][0] * il0, o[j][1] * il0, lo0);
        *(uint32_t*)(outh + (long)row0 * DMODEL + col) = hi0;
        *(uint32_t*)(outl + (long)row0 * DMODEL + col) = lo0;
        uint32_t lo1, hi1 = pack_hilo(o[j][2] * il1, o[j][3] * il1, lo1);
        *(uint32_t*)(outh + (long)row1 * DMODEL + col) = hi1;
        *(uint32_t*)(outl + (long)row1 * DMODEL + col) = lo1;
    }
}

// ---------------- bf16x3 split-precision tensor-core GEMM (round-4 body) ----------------
// EPI: 0=bias(optional), 1=bias+residual, 2=bias+gelu.  TB: B is [N,K].
// HILO: write Ch/Cl bf16 pair, else fp32 C.  z-strides az/bz/cz double as split-K.
template <int EPI, bool TB, int BN, bool HILO>
__global__ void __launch_bounds__(256)
gemm_bf3(const bf16* __restrict__ Ah, const bf16* __restrict__ Al,
         const bf16* __restrict__ Bh, const bf16* __restrict__ Bl,
         const float* __restrict__ bias, const float* __restrict__ res,
         float* __restrict__ C, bf16* __restrict__ Ch, bf16* __restrict__ Cl,
         int N, int K, int lda, int ldb, int ldc,
         long az, long bz, long cz) {
    constexpr int WN = BN / 4;
    constexpr int NA = WN / 8;
    constexpr int NP = NA / 2;
    constexpr int LDA = 40;
    constexpr int AHALF = 128 * LDA;
    constexpr int LDBN = BN + 8;
    constexpr int BSZ = TB ? BN * 40 : 32 * LDBN;
    constexpr int BOFF = 2 * AHALF;
    constexpr int STG = 2 * AHALF + 2 * BSZ;

    extern __shared__ bf16 smem_[];
    uint32_t sb = (uint32_t)__cvta_generic_to_shared(smem_);

    int z = blockIdx.z;
    Ah += (long)z * az; Al += (long)z * az;
    Bh += (long)z * bz; Bl += (long)z * bz;
    if (HILO) { Ch += (long)z * cz; Cl += (long)z * cz; }
    else      { C  += (long)z * cz; }

    int m0 = blockIdx.y * 128;
    int n0 = blockIdx.x * BN;
    int tid = threadIdx.x, lane = tid & 31, wid = tid >> 5;
    int wm = wid & 1, wn = wid >> 1;
    int g = lane >> 2, qi = lane & 3;

    float acc[4][NA][4];
#pragma unroll
    for (int i = 0; i < 4; i++)
#pragma unroll
        for (int j = 0; j < NA; j++)
#pragma unroll
            for (int u = 0; u < 4; u++) acc[i][j][u] = 0.f;

    auto load_tile = [&](int kt, int s) {
        int k0 = kt * 32;
        uint32_t stg = sb + (uint32_t)(s * STG * 2);
#pragma unroll
        for (int j = 0; j < 4; j++) {
            int fid = tid + j * 256;
            int arr = fid >> 9;
            int row = (fid >> 2) & 127;
            int cc  = fid & 3;
            uint32_t dst = stg + (uint32_t)((arr * AHALF + row * LDA + cc * 8) * 2);
            const bf16* src = (arr ? Al : Ah) + (long)(m0 + row) * lda + k0 + cc * 8;
            CPA16(dst, src, 16);
        }
        if (TB) {
#pragma unroll
            for (int j = 0; j < BN / 32; j++) {
                int fid = tid + j * 256;
                int arr = fid >> 9;
                int row = (fid >> 2) & 127;
                int cc  = fid & 3;
                int n = n0 + row;
                int ok = (n < N) ? 16 : 0;
                long nn = (n < N) ? n : (N - 1);
                uint32_t dst = stg + (uint32_t)((BOFF + arr * BSZ + row * 40 + cc * 8) * 2);
                const bf16* src = (arr ? Bl : Bh) + nn * (long)ldb + k0 + cc * 8;
                CPA16(dst, src, ok);
            }
        } else {
            constexpr int CPR = BN / 8;
            constexpr int TOT = 32 * CPR * 2;
#pragma unroll
            for (int j = 0; j < TOT / 256; j++) {
                int fid = tid + j * 256;
                int arr = fid / (32 * CPR);
                int rem = fid % (32 * CPR);
                int row = rem / CPR;
                int cc  = rem % CPR;
                uint32_t dst = stg + (uint32_t)((BOFF + arr * BSZ + row * LDBN + cc * 8) * 2);
                const bf16* src = (arr ? Bl : Bh) + (long)(k0 + row) * ldb + n0 + cc * 8;
                CPA16(dst, src, 16);
            }
        }
        asm volatile("cp.async.commit_group;\n");
    };

    int KT = K / 32;
    load_tile(0, 0);

    int arow = wm * 64 + (lane & 15);
    int acolh = (lane & 16) ? 8 : 0;
    int tb_row = wn * WN + (lane & 7) + ((lane & 16) ? 8 : 0);
    int tb_colh = (lane & 8) ? 8 : 0;
    int nt_rowk = (lane & 15);
    int nt_col = wn * WN + ((lane & 16) ? 8 : 0);

    for (int kt = 0; kt < KT; kt++) {
        int s = kt & 1;
        if (kt + 1 < KT) {
            load_tile(kt + 1, s ^ 1);
            asm volatile("cp.async.wait_group 1;\n");
        } else {
            asm volatile("cp.async.wait_group 0;\n");
        }
        __syncthreads();

        uint32_t stg = sb + (uint32_t)(s * STG * 2);

#pragma unroll
        for (int ks = 0; ks < 2; ks++) {
            uint32_t ah[4][4], al[4][4];
#pragma unroll
            for (int ma = 0; ma < 4; ma++) {
                uint32_t ad = stg + (uint32_t)((((arow + ma * 16) * LDA) + ks * 16 + acolh) * 2);
                ldsm4(ah[ma][0], ah[ma][1], ah[ma][2], ah[ma][3], ad);
                ldsm4(al[ma][0], al[ma][1], al[ma][2], al[ma][3], ad + AHALF * 2);
            }
            uint32_t bh[NA][2], bl[NA][2];
#pragma unroll
            for (int p = 0; p < NP; p++) {
                if (TB) {
                    uint32_t bd = stg + (uint32_t)((BOFF + (tb_row + p * 16) * 40 + ks * 16 + tb_colh) * 2);
                    ldsm4(bh[2 * p][0], bh[2 * p][1], bh[2 * p + 1][0], bh[2 * p + 1][1], bd);
                    ldsm4(bl[2 * p][0], bl[2 * p][1], bl[2 * p + 1][0], bl[2 * p + 1][1], bd + BSZ * 2);
                } else {
                    uint32_t bd = stg + (uint32_t)((BOFF + (ks * 16 + nt_rowk) * LDBN + nt_col + p * 16) * 2);
                    ldsm4t(bh[2 * p][0], bh[2 * p][1], bh[2 * p + 1][0], bh[2 * p + 1][1], bd);
                    ldsm4t(bl[2 * p][0], bl[2 * p][1], bl[2 * p + 1][0], bl[2 * p + 1][1], bd + BSZ * 2);
                }
            }
#pragma unroll
            for (int ma = 0; ma < 4; ma++)
#pragma unroll
                for (int nb = 0; nb < NA; nb++) {
                    mma16816(acc[ma][nb], ah[ma], bh[nb]);
                    mma16816(acc[ma][nb], ah[ma], bl[nb]);
                    mma16816(acc[ma][nb], al[ma], bh[nb]);
                }
        }
        __syncthreads();
    }

#pragma unroll
    for (int ma = 0; ma < 4; ma++) {
        int r0 = m0 + wm * 64 + ma * 16 + g;
#pragma unroll
        for (int nb = 0; nb < NA; nb++) {
            int c0 = n0 + wn * WN + nb * 8 + 2 * qi;
#pragma unroll
            for (int hf = 0; hf < 2; hf++) {
                int r = r0 + hf * 8;
                float v0 = acc[ma][nb][hf * 2 + 0];
                float v1 = acc[ma][nb][hf * 2 + 1];
                if (bias) { v0 += bias[c0]; v1 += bias[c0 + 1]; }
                if (EPI == 1) {
                    v0 += res[(long)r * ldc + c0];
                    v1 += res[(long)r * ldc + c0 + 1];
                }
                if (EPI == 2) { v0 = gelu_f(v0); v1 = gelu_f(v1); }
                if (HILO) {
                    bf16 h0, l0x, h1, l1x;
                    split_bf(v0, h0, l0x); split_bf(v1, h1, l1x);
                    bf162 hv; hv.x = h0; hv.y = h1;
                    bf162 lv; lv.x = l0x; lv.y = l1x;
                    *(bf162*)(Ch + (long)r * ldc + c0) = hv;
                    *(bf162*)(Cl + (long)r * ldc + c0) = lv;
                } else {
                    if (c0 < N)     C[(long)r * ldc + c0]     = v0;
                    if (c0 + 1 < N) C[(long)r * ldc + c0 + 1] = v1;
                }
            }
        }
    }
}

// ---------------- launch helper ----------------
template <int EPI, bool TB, int BN, bool HILO>
static inline void launch_gemm(dim3 grid,
                               const bf16* Ah, const bf16* Al,
                               const bf16* Bh, const bf16* Bl,
                               const float* bias, const float* res,
                               float* C, bf16* Ch, bf16* Cl,
                               int N, int K, int lda, int ldb, int ldc,
                               long az, long bz, long cz) {
    constexpr int LDBN = BN + 8;
    constexpr int BSZ = TB ? BN * 40 : 32 * LDBN;
    constexpr int STG = 2 * 128 * 40 + 2 * BSZ;
    constexpr int BYTES = STG * 2 * 2;
    cudaFuncSetAttribute(gemm_bf3<EPI, TB, BN, HILO>,
                         cudaFuncAttributeMaxDynamicSharedMemorySize, BYTES);
    gemm_bf3<EPI, TB, BN, HILO><<<grid, 256, BYTES>>>(
        Ah, Al, Bh, Bl, bias, res, C, Ch, Cl, N, K, lda, ldb, ldc, az, bz, cz);
}

static inline void convert_w(const float* src, bf16* hi, bf16* lo, long n) {
    long n4 = n / 4;
    f2bf_kernel<<<(unsigned)((n4 + 255) / 256), 256>>>(
        (const float4*)src, (bf162*)hi, (bf162*)lo, n4);
}

// ---------------- host launcher ----------------
extern "C" void kernel_launch(void* const* d_in, const int* in_sizes, int n_in,
                              void* d_out, int out_size) {
    const int*   ids    = (const int*)d_in[0];
    const int*   sp     = (const int*)d_in[1];
    // d_in[2..4]: block table / kv pools — identity map at start_pos=0, pools input-only.
    const float* wte    = (const float*)d_in[5];
    const float* wpe    = (const float*)d_in[6];
    const float* ln1_g  = (const float*)d_in[7];
    const float* ln1_b  = (const float*)d_in[8];
    const float* attn_w = (const float*)d_in[9];
    const float* attn_b = (const float*)d_in[10];
    const float* attn_pw= (const float*)d_in[11];
    const float* attn_pb= (const float*)d_in[12];
    const float* ln2_g  = (const float*)d_in[13];
    const float* ln2_b  = (const float*)d_in[14];
    const float* fc_w   = (const float*)d_in[15];
    const float* fc_b   = (const float*)d_in[16];
    const float* proj_w = (const float*)d_in[17];
    const float* proj_b = (const float*)d_in[18];
    const float* lnf_g  = (const float*)d_in[19];
    const float* lnf_b  = (const float*)d_in[20];
    float* out = (float*)d_out;

    float *x, *part;
    bf16 *hh, *hl, *qh, *ql, *ath, *atl, *fh, *fl;
    bf16 *wqh, *wql, *wph, *wpl, *wfh, *wfl, *wjh, *wjl, *wth, *wtl;
    cudaGetSymbolAddress((void**)&x,    g_x);
    cudaGetSymbolAddress((void**)&part, g_part);
    cudaGetSymbolAddress((void**)&hh,  g_h_hi);   cudaGetSymbolAddress((void**)&hl,  g_h_lo);
    cudaGetSymbolAddress((void**)&qh,  g_qkv_hi); cudaGetSymbolAddress((void**)&ql,  g_qkv_lo);
    cudaGetSymbolAddress((void**)&ath, g_attn_hi);cudaGetSymbolAddress((void**)&atl, g_attn_lo);
    cudaGetSymbolAddress((void**)&fh,  g_fc_hi);  cudaGetSymbolAddress((void**)&fl,  g_fc_lo);
    cudaGetSymbolAddress((void**)&wqh, w_qkv_hi); cudaGetSymbolAddress((void**)&wql, w_qkv_lo);
    cudaGetSymbolAddress((void**)&wph, w_pw_hi);  cudaGetSymbolAddress((void**)&wpl, w_pw_lo);
    cudaGetSymbolAddress((void**)&wfh, w_fc_hi);  cudaGetSymbolAddress((void**)&wfl, w_fc_lo);
    cudaGetSymbolAddress((void**)&wjh, w_pj_hi);  cudaGetSymbolAddress((void**)&wjl, w_pj_lo);
    cudaGetSymbolAddress((void**)&wth, w_te_hi);  cudaGetSymbolAddress((void**)&wtl, w_te_lo);

    const int D = DMODEL;
    const long MN = (long)LSEQ * D;

    convert_w(attn_w,  wqh, wql, (long)NLAYER * D * 3 * D);
    convert_w(attn_pw, wph, wpl, (long)NLAYER * D * D);
    convert_w(fc_w,    wfh, wfl, (long)NLAYER * D * 4 * D);
    convert_w(proj_w,  wjh, wjl, (long)NLAYER * 4 * D * D);
    convert_w(wte, wth, wtl, (long)VOCAB * D);

    embed_kernel<<<LSEQ, 256>>>(ids, sp, wte, wpe);
    ln_kernel<<<LSEQ, 256>>>(x, hh, hl, ln1_g, ln1_b);   // layer-0 ln1

    for (int i = 0; i < NLAYER; i++) {
        // qkv = h @ Wqkv + b -> hi/lo   [1024, 2304]   144 CTAs
        launch_gemm<0, false, 128, true>(dim3(18, 8, 1),
            hh, hl, wqh + (long)i * D * 3 * D, wql + (long)i * D * 3 * D,
            attn_b + (long)i * 3 * D, nullptr, nullptr, qh, ql,
            3 * D, D, D, 3 * D, 3 * D, 0, 0, 0);

        // fused flash attention -> attn hi/lo
        flash_kernel<<<dim3(LSEQ / 64, NHEAD), 128>>>(qh, ql, ath, atl);

        // pw partials (split-K=3): part[z] = attn @ Wp[z-chunk]   144 CTAs
        launch_gemm<0, false, 128, false>(dim3(6, 8, 3),
            ath, atl, wph + (long)i * D * D, wpl + (long)i * D * D,
            nullptr, nullptr, part, nullptr, nullptr,
            D, D / 3, D, D, D, D / 3, (long)(D / 3) * D, MN);

        // x += pb + sum(parts); h = ln2(x)
        reduce_ln_kernel<<<LSEQ, 256>>>(part, attn_pb + (long)i * D, x,
                                        ln2_g + (long)i * D, ln2_b + (long)i * D, hh, hl);

        // fc = gelu(h @ Wfc + b) -> hi/lo  [1024, 3072]   BN=192, 128 CTAs
        launch_gemm<2, false, 192, true>(dim3(16, 8, 1),
            hh, hl, wfh + (long)i * D * 4 * D, wfl + (long)i * D * 4 * D,
            fc_b + (long)i * 4 * D, nullptr, nullptr, fh, fl,
            4 * D, D, D, 4 * D, 4 * D, 0, 0, 0);

        // pj partials (split-K=3 over K=3072): 144 CTAs
        launch_gemm<0, false, 128, false>(dim3(6, 8, 3),
            fh, fl, wjh + (long)i * 4 * D * D, wjl + (long)i * 4 * D * D,
            nullptr, nullptr, part, nullptr, nullptr,
            D, 4 * D / 3, 4 * D, D, D, 4 * D / 3, (long)(4 * D / 3) * D, MN);

        // x += pb + sum(parts); h = ln1_{i+1}(x) or lnf(x)
        const float* ng = (i + 1 < NLAYER) ? ln1_g + (long)(i + 1) * D : lnf_g;
        const float* nb = (i + 1 < NLAYER) ? ln1_b + (long)(i + 1) * D : lnf_b;
        reduce_ln_kernel<<<LSEQ, 256>>>(part, proj_b + (long)i * D, x, ng, nb, hh, hl);
    }

    // logits = h @ wteᵀ  [1024, 50257]
    launch_gemm<0, true, 128, false>(dim3((VOCAB + 127) / 128, 8, 1),
        hh, hl, wth, wtl, nullptr, nullptr, out, nullptr, nullptr,
        VOCAB, D, D, D, VOCAB, 0, 0, 0);
}